// round 7
// baseline (speedup 1.0000x reference)
#include <cuda_runtime.h>
#include <cuda_fp16.h>
#include <math.h>
#include <stdint.h>

#define SEQ     2048
#define DMODEL  512
#define NH      8
#define DH      64
#define BATCH   2
#define MTOT    4096

// ---------------- scratch (__device__ globals, allocation-free) -------------
__device__ __half g_xh[MTOT * DMODEL];
__device__ __half g_xl[MTOT * DMODEL];
__device__ __half g_wh[3 * DMODEL * DMODEL];   // [Wq;Wk;Wv] rows 0..1535 (hi)
__device__ __half g_wl[3 * DMODEL * DMODEL];   // lo used only for Wv range
__device__ __half g_oh[DMODEL * DMODEL];
__device__ __half g_ol[DMODEL * DMODEL];
__device__ __half g_vh[MTOT * DMODEL];
__device__ __half g_vl[MTOT * DMODEL];
__device__ __half g_zh[MTOT * DMODEL];
__device__ __half g_zl[MTOT * DMODEL];
__device__ float  g_sa[16 * SEQ];
__device__ float  g_sc[16 * SEQ];
__device__ float  g_cs[16 * 64 * 64];   // per-(bh, chunk32, dh) V column sums

// ---------------------------------------------------------------------------
__device__ __forceinline__ uint32_t smem_u32(const void* p) {
    uint32_t a;
    asm("{ .reg .u64 t; cvta.to.shared.u64 t, %1; cvt.u32.u64 %0, t; }"
        : "=r"(a) : "l"(p));
    return a;
}

#define CPASYNC(d, s) \
    asm volatile("cp.async.cg.shared.global [%0], [%1], 16;" \
                 :: "r"(d), "l"(s) : "memory")

#define LDSM4(r, a) \
    asm volatile("ldmatrix.sync.aligned.m8n8.x4.shared.b16 {%0,%1,%2,%3}, [%4];" \
                 : "=r"((r)[0]), "=r"((r)[1]), "=r"((r)[2]), "=r"((r)[3]) \
                 : "r"(a))

#define MMA(d, a, b0, b1) \
    asm volatile("mma.sync.aligned.m16n8k16.row.col.f32.f16.f16.f32 " \
                 "{%0,%1,%2,%3},{%4,%5,%6,%7},{%8,%9},{%0,%1,%2,%3};" \
                 : "+f"((d)[0]), "+f"((d)[1]), "+f"((d)[2]), "+f"((d)[3]) \
                 : "r"((a)[0]), "r"((a)[1]), "r"((a)[2]), "r"((a)[3]), \
                   "r"(b0), "r"(b1))

#define SROW 72                       // padded row in halves (144 B)
#define MATS (128 * SROW)             // halves per matrix tile

// ---------------------------------------------------------------------------
// fp32 -> fp16 hi/lo conversion (lo skipped for Wq/Wk)
// ---------------------------------------------------------------------------
__global__ __launch_bounds__(256) void convert_all(
    const float* __restrict__ x,  const float* __restrict__ wq,
    const float* __restrict__ wk, const float* __restrict__ wv,
    const float* __restrict__ wo)
{
    int t = blockIdx.x * 256 + threadIdx.x;       // float4 index, 786432 total
    const float* src;
    __half *dh, *dl;
    int idx;
    bool wantLo = true;
    if (t < 524288)      { src = x;  dh = g_xh;          dl = g_xl;          idx = t; }
    else if (t < 589824) { src = wq; dh = g_wh;          dl = g_wl;          idx = t - 524288; wantLo = false; }
    else if (t < 655360) { src = wk; dh = g_wh + 262144; dl = g_wl + 262144; idx = t - 589824; wantLo = false; }
    else if (t < 720896) { src = wv; dh = g_wh + 524288; dl = g_wl + 524288; idx = t - 655360; }
    else                 { src = wo; dh = g_oh;          dl = g_ol;          idx = t - 720896; }

    float4 v = ((const float4*)src)[idx];
    __half h0 = __float2half_rn(v.x), h1 = __float2half_rn(v.y);
    __half h2 = __float2half_rn(v.z), h3 = __float2half_rn(v.w);
    __half2* ph = (__half2*)(dh + idx * 4);
    ph[0] = __halves2half2(h0, h1); ph[1] = __halves2half2(h2, h3);
    if (wantLo) {
        __half l0 = __float2half_rn(v.x - __half2float(h0));
        __half l1 = __float2half_rn(v.y - __half2float(h1));
        __half l2 = __float2half_rn(v.z - __half2float(h2));
        __half l3 = __float2half_rn(v.w - __half2float(h3));
        __half2* pl = (__half2*)(dl + idx * 4);
        pl[0] = __halves2half2(l0, l1); pl[1] = __halves2half2(l2, l3);
    }
}

// ---------------------------------------------------------------------------
// Fused QK-diag + V projection kernel. grid (8, 32):
//   bx 0..3: QK branch — s[m,h] = Qrow.Krow computed in-register, writes sa/sc
//   bx 4..7: V branch  — fp16x3 GEMM, epilogue writes vh/vl + 32-row chunk sums
// ---------------------------------------------------------------------------
__global__ __launch_bounds__(256) void qkv_fused(
    const __half* __restrict__ xh, const __half* __restrict__ xl,
    const __half* __restrict__ wh, const __half* __restrict__ wl)
{
    extern __shared__ __half sm[];
    const uint32_t sb = smem_u32(sm);
    const int tid = threadIdx.x;
    const int lane = tid & 31, wid = tid >> 5;
    const int wm = wid & 3, wn = wid >> 2;
    const int m0 = blockIdx.y * 128;

    const int lr = tid >> 1, lp = tid & 1;
    const uint32_t dst0 = sb + (uint32_t)(lr * SROW + lp * 32) * 2;

    const uint32_t a_row_off =
        (uint32_t)((wm * 32 + (lane & 15)) * SROW) * 2 + (uint32_t)((lane >> 4) * 16);
    const int bn = wn * 64 + (lane & 7) + ((lane >> 4) << 3);
    const uint32_t b_row_off =
        (uint32_t)(bn * SROW) * 2 + (uint32_t)(((lane >> 3) & 1) * 16);

    if (blockIdx.x < 4) {
        // ================= QK-diagonal branch (plain fp16, 3 mats) ==========
        constexpr uint32_t BUFB = 3u * MATS * 2;
        const int n0 = blockIdx.x * 128;
        const __half* gA = xh + (size_t)(m0 + lr) * 512 + lp * 32;
        const __half* gQ = wh + (size_t)(n0 + lr) * 512 + lp * 32;              // Wq
        const __half* gK = wh + 512 * 512 + (size_t)(n0 + lr) * 512 + lp * 32;  // Wk

#define LOADCHUNK_QK(c, b) { \
        const uint32_t d = dst0 + (uint32_t)(b) * BUFB; \
        const int ko = (c) * 64; \
        _Pragma("unroll") \
        for (int j = 0; j < 4; j++) { \
            CPASYNC(d + 0 * MATS * 2 + j * 16, gA + ko + j * 8); \
            CPASYNC(d + 1 * MATS * 2 + j * 16, gQ + ko + j * 8); \
            CPASYNC(d + 2 * MATS * 2 + j * 16, gK + ko + j * 8); \
        } }

        float aq[2][8][4], ak[2][8][4];
#pragma unroll
        for (int i = 0; i < 2; i++)
#pragma unroll
            for (int j = 0; j < 8; j++)
#pragma unroll
                for (int k = 0; k < 4; k++) { aq[i][j][k] = 0.0f; ak[i][j][k] = 0.0f; }

        LOADCHUNK_QK(0, 0);
        asm volatile("cp.async.commit_group;" ::: "memory");

        for (int c = 0; c < 8; c++) {
            if (c < 7) {
                LOADCHUNK_QK(c + 1, (c + 1) & 1);
                asm volatile("cp.async.commit_group;" ::: "memory");
                asm volatile("cp.async.wait_group 1;" ::: "memory");
            } else {
                asm volatile("cp.async.wait_group 0;" ::: "memory");
            }
            __syncthreads();

            const uint32_t base = sb + (uint32_t)(c & 1) * BUFB;
#pragma unroll
            for (int kk = 0; kk < 4; kk++) {
                const uint32_t aA = base + a_row_off + kk * 32;
                uint32_t a0[4], a1[4];
                LDSM4(a0, aA);
                LDSM4(a1, aA + 16 * SROW * 2);

                const uint32_t bQ = base + 1 * MATS * 2 + b_row_off + kk * 32;
                const uint32_t bK = base + 2 * MATS * 2 + b_row_off + kk * 32;
#pragma unroll
                for (int jp = 0; jp < 4; jp++) {
                    uint32_t bq[4], bk[4];
                    LDSM4(bq, bQ + jp * 16 * SROW * 2);
                    LDSM4(bk, bK + jp * 16 * SROW * 2);
                    MMA(aq[0][2 * jp],     a0, bq[0], bq[1]);
                    MMA(aq[1][2 * jp],     a1, bq[0], bq[1]);
                    MMA(aq[0][2 * jp + 1], a0, bq[2], bq[3]);
                    MMA(aq[1][2 * jp + 1], a1, bq[2], bq[3]);
                    MMA(ak[0][2 * jp],     a0, bk[0], bk[1]);
                    MMA(ak[1][2 * jp],     a1, bk[0], bk[1]);
                    MMA(ak[0][2 * jp + 1], a0, bk[2], bk[3]);
                    MMA(ak[1][2 * jp + 1], a1, bk[2], bk[3]);
                }
            }
            __syncthreads();
        }

        // Epilogue: per-row head dot (warp's 64 cols = one head)
        const int h = blockIdx.x * 2 + wn;
#pragma unroll
        for (int j = 0; j < 4; j++) {
            const int mi = j >> 1, o = (j & 1) * 2;
            float p = 0.0f;
#pragma unroll
            for (int ni = 0; ni < 8; ni++)
                p += aq[mi][ni][o] * ak[mi][ni][o]
                   + aq[mi][ni][o + 1] * ak[mi][ni][o + 1];
            p += __shfl_xor_sync(0xFFFFFFFF, p, 1);
            p += __shfl_xor_sync(0xFFFFFFFF, p, 2);
            if ((lane & 3) == 0) {
                const int m = m0 + wm * 32 + (lane >> 2) + (j >> 1) * 16 + (j & 1) * 8;
                const int b = m >> 11, q = m & 2047;
                float sd = p * 0.125f;
                int cnt = SEQ - 1 - q;
                float mx = (cnt > 0) ? fmaxf(sd, 0.0f) : sd;
                float ed = expf(sd - mx);
                float eo = (cnt > 0) ? expf(-mx) : 0.0f;
                float Z = ed + (float)cnt * eo;
                g_sa[(b * 8 + h) * SEQ + q] = ed / Z;
                g_sc[(b * 8 + h) * SEQ + q] = eo / Z;
            }
        }
    } else {
        // ================= V branch (fp16x3, 4 mats, fused chunk sums) ======
        constexpr uint32_t BUFB = 4u * MATS * 2;
        const int n0 = (blockIdx.x - 4) * 128;
        const __half* gAh = xh + (size_t)(m0 + lr) * 512 + lp * 32;
        const __half* gAl = xl + (size_t)(m0 + lr) * 512 + lp * 32;
        const __half* gBh = wh + 1024 * 512 + (size_t)(n0 + lr) * 512 + lp * 32;
        const __half* gBl = wl + 1024 * 512 + (size_t)(n0 + lr) * 512 + lp * 32;

#define LOADCHUNK3(c, b) { \
        const uint32_t d = dst0 + (uint32_t)(b) * BUFB; \
        const int ko = (c) * 64; \
        _Pragma("unroll") \
        for (int j = 0; j < 4; j++) { \
            CPASYNC(d + 0 * MATS * 2 + j * 16, gAh + ko + j * 8); \
            CPASYNC(d + 1 * MATS * 2 + j * 16, gAl + ko + j * 8); \
            CPASYNC(d + 2 * MATS * 2 + j * 16, gBh + ko + j * 8); \
            CPASYNC(d + 3 * MATS * 2 + j * 16, gBl + ko + j * 8); \
        } }

        float acc[2][8][4];
#pragma unroll
        for (int i = 0; i < 2; i++)
#pragma unroll
            for (int j = 0; j < 8; j++)
#pragma unroll
                for (int k = 0; k < 4; k++) acc[i][j][k] = 0.0f;

        LOADCHUNK3(0, 0);
        asm volatile("cp.async.commit_group;" ::: "memory");

        for (int c = 0; c < 8; c++) {
            if (c < 7) {
                LOADCHUNK3(c + 1, (c + 1) & 1);
                asm volatile("cp.async.commit_group;" ::: "memory");
                asm volatile("cp.async.wait_group 1;" ::: "memory");
            } else {
                asm volatile("cp.async.wait_group 0;" ::: "memory");
            }
            __syncthreads();

            const uint32_t base = sb + (uint32_t)(c & 1) * BUFB;
#pragma unroll
            for (int kk = 0; kk < 4; kk++) {
                const uint32_t aH = base + a_row_off + kk * 32;
                const uint32_t aL = aH + MATS * 2;
                uint32_t ah0[4], ah1[4], al0[4], al1[4];
                LDSM4(ah0, aH);
                LDSM4(ah1, aH + 16 * SROW * 2);
                LDSM4(al0, aL);
                LDSM4(al1, aL + 16 * SROW * 2);

                const uint32_t bH = base + 2 * MATS * 2 + b_row_off + kk * 32;
                const uint32_t bL = bH + MATS * 2;
#pragma unroll
                for (int jp = 0; jp < 4; jp++) {
                    uint32_t bh[4], bl[4];
                    LDSM4(bh, bH + jp * 16 * SROW * 2);
                    LDSM4(bl, bL + jp * 16 * SROW * 2);
                    MMA(acc[0][2 * jp],     ah0, bh[0], bh[1]);
                    MMA(acc[1][2 * jp],     ah1, bh[0], bh[1]);
                    MMA(acc[0][2 * jp + 1], ah0, bh[2], bh[3]);
                    MMA(acc[1][2 * jp + 1], ah1, bh[2], bh[3]);
                    MMA(acc[0][2 * jp],     al0, bh[0], bh[1]);
                    MMA(acc[1][2 * jp],     al1, bh[0], bh[1]);
                    MMA(acc[0][2 * jp + 1], al0, bh[2], bh[3]);
                    MMA(acc[1][2 * jp + 1], al1, bh[2], bh[3]);
                    MMA(acc[0][2 * jp],     ah0, bl[0], bl[1]);
                    MMA(acc[1][2 * jp],     ah1, bl[0], bl[1]);
                    MMA(acc[0][2 * jp + 1], ah0, bl[2], bl[3]);
                    MMA(acc[1][2 * jp + 1], ah1, bl[2], bl[3]);
                }
            }
            __syncthreads();
        }

        // Epilogue 1: store vh/vl (fp16 hi/lo)
        const int r0 = m0 + wm * 32 + (lane >> 2);
        const int cb = n0 + wn * 64 + (lane & 3) * 2;
#pragma unroll
        for (int mi = 0; mi < 2; mi++) {
#pragma unroll
            for (int ni = 0; ni < 8; ni++) {
                const int cg = cb + ni * 8;
#pragma unroll
                for (int rr = 0; rr < 2; rr++) {
                    const int r = r0 + mi * 16 + rr * 8;
                    float v0 = acc[mi][ni][rr * 2], v1 = acc[mi][ni][rr * 2 + 1];
                    __half h0 = __float2half_rn(v0), h1 = __float2half_rn(v1);
                    __half l0 = __float2half_rn(v0 - __half2float(h0));
                    __half l1 = __float2half_rn(v1 - __half2float(h1));
                    *(__half2*)&g_vh[(size_t)r * 512 + cg] = __halves2half2(h0, h1);
                    *(__half2*)&g_vl[(size_t)r * 512 + cg] = __halves2half2(l0, l1);
                }
            }
        }

        // Epilogue 2: 32-row chunk sums (warp tile = exactly one chunk x one head)
        const int b = m0 >> 11;
        const int chunk = ((m0 & 2047) >> 5) + wm;
        const int hh = (n0 + wn * 64) >> 6;
        float* csbase = g_cs + ((size_t)(b * 8 + hh) * 64 + chunk) * 64;
#pragma unroll
        for (int ni = 0; ni < 8; ni++) {
            float s0 = acc[0][ni][0] + acc[0][ni][2] + acc[1][ni][0] + acc[1][ni][2];
            float s1 = acc[0][ni][1] + acc[0][ni][3] + acc[1][ni][1] + acc[1][ni][3];
#pragma unroll
            for (int st = 4; st < 32; st <<= 1) {
                s0 += __shfl_xor_sync(0xFFFFFFFF, s0, st);
                s1 += __shfl_xor_sync(0xFFFFFFFF, s1, st);
            }
            if (lane < 4) {
                const int dh = (lane << 1) + ni * 8;   // (lane&3)*2 + ni*8
                *(float2*)&csbase[dh] = make_float2(s0, s1);
            }
        }
    }
}

// ---------------------------------------------------------------------------
// HMMA fp16x3 GEMM (hi/lo compensated): C = A.B^T  — output projection
// ---------------------------------------------------------------------------
__global__ __launch_bounds__(256) void gemm_mma3(
    const __half* __restrict__ Ah, const __half* __restrict__ Al,
    const __half* __restrict__ Bh, const __half* __restrict__ Bl,
    float* __restrict__ C)
{
    constexpr uint32_t BUFB = 4u * MATS * 2;

    extern __shared__ __half sm[];
    const uint32_t sb = smem_u32(sm);
    const int tid = threadIdx.x;
    const int lane = tid & 31, wid = tid >> 5;
    const int wm = wid & 3, wn = wid >> 2;
    const int n0 = blockIdx.x * 128, m0 = blockIdx.y * 128;

    const int lr = tid >> 1, lp = tid & 1;
    const __half* gAh = Ah + (size_t)(m0 + lr) * 512 + lp * 32;
    const __half* gAl = Al + (size_t)(m0 + lr) * 512 + lp * 32;
    const __half* gBh = Bh + (size_t)(n0 + lr) * 512 + lp * 32;
    const __half* gBl = Bl + (size_t)(n0 + lr) * 512 + lp * 32;
    const uint32_t dst0 = sb + (uint32_t)(lr * SROW + lp * 32) * 2;

#define LOADCHUNKO(c, b) { \
        const uint32_t d = dst0 + (uint32_t)(b) * BUFB; \
        const int ko = (c) * 64; \
        _Pragma("unroll") \
        for (int j = 0; j < 4; j++) { \
            CPASYNC(d + 0 * MATS * 2 + j * 16, gAh + ko + j * 8); \
            CPASYNC(d + 1 * MATS * 2 + j * 16, gAl + ko + j * 8); \
            CPASYNC(d + 2 * MATS * 2 + j * 16, gBh + ko + j * 8); \
            CPASYNC(d + 3 * MATS * 2 + j * 16, gBl + ko + j * 8); \
        } }

    float acc[2][8][4];
#pragma unroll
    for (int i = 0; i < 2; i++)
#pragma unroll
        for (int j = 0; j < 8; j++)
#pragma unroll
            for (int k = 0; k < 4; k++) acc[i][j][k] = 0.0f;

    LOADCHUNKO(0, 0);
    asm volatile("cp.async.commit_group;" ::: "memory");

    const uint32_t a_row_off =
        (uint32_t)((wm * 32 + (lane & 15)) * SROW) * 2 + (uint32_t)((lane >> 4) * 16);
    const int bn = wn * 64 + (lane & 7) + ((lane >> 4) << 3);
    const uint32_t b_row_off =
        (uint32_t)(bn * SROW) * 2 + (uint32_t)(((lane >> 3) & 1) * 16);

    for (int c = 0; c < 8; c++) {
        if (c < 7) {
            LOADCHUNKO(c + 1, (c + 1) & 1);
            asm volatile("cp.async.commit_group;" ::: "memory");
            asm volatile("cp.async.wait_group 1;" ::: "memory");
        } else {
            asm volatile("cp.async.wait_group 0;" ::: "memory");
        }
        __syncthreads();

        const uint32_t base = sb + (uint32_t)(c & 1) * BUFB;
#pragma unroll
        for (int kk = 0; kk < 4; kk++) {
            const uint32_t aH = base + a_row_off + kk * 32;
            const uint32_t aL = aH + MATS * 2;
            uint32_t ah0[4], ah1[4], al0[4], al1[4];
            LDSM4(ah0, aH);
            LDSM4(ah1, aH + 16 * SROW * 2);
            LDSM4(al0, aL);
            LDSM4(al1, aL + 16 * SROW * 2);

            const uint32_t bH = base + 2 * MATS * 2 + b_row_off + kk * 32;
            const uint32_t bL = bH + MATS * 2;
#pragma unroll
            for (int jp = 0; jp < 4; jp++) {
                uint32_t bh[4], bl[4];
                LDSM4(bh, bH + jp * 16 * SROW * 2);
                LDSM4(bl, bL + jp * 16 * SROW * 2);
                MMA(acc[0][2 * jp],     ah0, bh[0], bh[1]);
                MMA(acc[1][2 * jp],     ah1, bh[0], bh[1]);
                MMA(acc[0][2 * jp + 1], ah0, bh[2], bh[3]);
                MMA(acc[1][2 * jp + 1], ah1, bh[2], bh[3]);
                MMA(acc[0][2 * jp],     al0, bh[0], bh[1]);
                MMA(acc[1][2 * jp],     al1, bh[0], bh[1]);
                MMA(acc[0][2 * jp + 1], al0, bh[2], bh[3]);
                MMA(acc[1][2 * jp + 1], al1, bh[2], bh[3]);
                MMA(acc[0][2 * jp],     ah0, bl[0], bl[1]);
                MMA(acc[1][2 * jp],     ah1, bl[0], bl[1]);
                MMA(acc[0][2 * jp + 1], ah0, bl[2], bl[3]);
                MMA(acc[1][2 * jp + 1], ah1, bl[2], bl[3]);
            }
        }
        __syncthreads();
    }

    const int r0 = m0 + wm * 32 + (lane >> 2);
    const int cb = n0 + wn * 64 + (lane & 3) * 2;
#pragma unroll
    for (int mi = 0; mi < 2; mi++) {
        const int r = r0 + mi * 16;
#pragma unroll
        for (int ni = 0; ni < 8; ni++) {
            const int cg = cb + ni * 8;
            *(float2*)&C[(size_t)r * 512 + cg] =
                make_float2(acc[mi][ni][0], acc[mi][ni][1]);
            *(float2*)&C[(size_t)(r + 8) * 512 + cg] =
                make_float2(acc[mi][ni][2], acc[mi][ni][3]);
        }
    }
}

// ---------------------------------------------------------------------------
// Scan: z[q] = a_q*v[q] + c_q*suffix_{p>q} v[p]
// ---------------------------------------------------------------------------
__global__ __launch_bounds__(256) void v_scan()
{
    int bh = blockIdx.y;
    int chunk = blockIdx.x * 4 + (threadIdx.x >> 6);
    int dh = threadIdx.x & 63;
    int b = bh >> 3, h = bh & 7;

    float run = 0.0f;
    const float* cs = g_cs + (size_t)bh * 64 * 64 + dh;
    for (int c2 = chunk + 1; c2 < 64; c2++)
        run += cs[(size_t)c2 * 64];

    const float* sa = g_sa + bh * SEQ;
    const float* sc = g_sc + bh * SEQ;
    const int q0 = chunk * 32;
#pragma unroll 4
    for (int i = 31; i >= 0; i--) {
        int q = q0 + i;
        size_t row = (size_t)(b * SEQ + q) * DMODEL + h * DH + dh;
        float v = __half2float(g_vh[row]) + __half2float(g_vl[row]);
        float z = sa[q] * v + sc[q] * run;
        __half zh = __float2half_rn(z);
        g_zh[row] = zh;
        g_zl[row] = __float2half_rn(z - __half2float(zh));
        run += v;
    }
}

// ---------------------------------------------------------------------------
extern "C" void kernel_launch(void* const* d_in, const int* in_sizes, int n_in,
                              void* d_out, int out_size)
{
    const float* x  = (const float*)d_in[0];
    const float* WQ = (const float*)d_in[1];
    const float* WK = (const float*)d_in[2];
    const float* WV = (const float*)d_in[3];
    const float* WO = (const float*)d_in[4];
    float* out = (float*)d_out;

    const int SMEMF = 2 * 4 * MATS * 2;   // 147456 B (max of both branches)
    cudaFuncSetAttribute(qkv_fused, cudaFuncAttributeMaxDynamicSharedMemorySize,
                         SMEMF);
    cudaFuncSetAttribute(gemm_mma3, cudaFuncAttributeMaxDynamicSharedMemorySize,
                         SMEMF);

    __half *xh, *xl, *wh, *wl, *oh, *ol, *zh, *zl;
    cudaGetSymbolAddress((void**)&xh, g_xh);
    cudaGetSymbolAddress((void**)&xl, g_xl);
    cudaGetSymbolAddress((void**)&wh, g_wh);
    cudaGetSymbolAddress((void**)&wl, g_wl);
    cudaGetSymbolAddress((void**)&oh, g_oh);
    cudaGetSymbolAddress((void**)&ol, g_ol);
    cudaGetSymbolAddress((void**)&zh, g_zh);
    cudaGetSymbolAddress((void**)&zl, g_zl);

    convert_all<<<3072, 256>>>(x, WQ, WK, WV, WO);

    // Fused: QK-diag (bx 0..3) + V projection w/ chunk sums (bx 4..7)
    qkv_fused<<<dim3(8, 32), 256, SMEMF>>>(xh, xl, wh, wl);

    v_scan<<<dim3(16, 16), 256>>>();

    // Output projection (fp16x3)
    gemm_mma3<<<dim3(4, 32), 256, SMEMF>>>(zh, zl, oh, ol, out);
}

// round 8
// speedup vs baseline: 1.0541x; 1.0541x over previous
#include <cuda_runtime.h>
#include <cuda_fp16.h>
#include <math.h>
#include <stdint.h>

#define SEQ     2048
#define DMODEL  512
#define NH      8
#define DH      64
#define BATCH   2
#define MTOT    4096

// ---------------- scratch (__device__ globals, allocation-free) -------------
__device__ __half g_xh[MTOT * DMODEL];
__device__ __half g_xl[MTOT * DMODEL];
__device__ __half g_wh[3 * DMODEL * DMODEL];   // [Wq;Wk;Wv] rows 0..1535 (hi)
__device__ __half g_wl[3 * DMODEL * DMODEL];   // lo used only for Wv range
__device__ __half g_oh[DMODEL * DMODEL];
__device__ __half g_ol[DMODEL * DMODEL];
__device__ __half g_vh[MTOT * DMODEL];
__device__ __half g_vl[MTOT * DMODEL];
__device__ __half g_zh[MTOT * DMODEL];
__device__ __half g_zl[MTOT * DMODEL];
__device__ float  g_sa[16 * SEQ];
__device__ float  g_sc[16 * SEQ];
__device__ float  g_cs[16 * 64 * 64];   // per-(bh, chunk32, dh) V column sums

// ---------------------------------------------------------------------------
__device__ __forceinline__ uint32_t smem_u32(const void* p) {
    uint32_t a;
    asm("{ .reg .u64 t; cvta.to.shared.u64 t, %1; cvt.u32.u64 %0, t; }"
        : "=r"(a) : "l"(p));
    return a;
}

#define CPASYNC(d, s) \
    asm volatile("cp.async.cg.shared.global [%0], [%1], 16;" \
                 :: "r"(d), "l"(s) : "memory")

#define LDSM4(r, a) \
    asm volatile("ldmatrix.sync.aligned.m8n8.x4.shared.b16 {%0,%1,%2,%3}, [%4];" \
                 : "=r"((r)[0]), "=r"((r)[1]), "=r"((r)[2]), "=r"((r)[3]) \
                 : "r"(a))

#define MMA(d, a, b0, b1) \
    asm volatile("mma.sync.aligned.m16n8k16.row.col.f32.f16.f16.f32 " \
                 "{%0,%1,%2,%3},{%4,%5,%6,%7},{%8,%9},{%0,%1,%2,%3};" \
                 : "+f"((d)[0]), "+f"((d)[1]), "+f"((d)[2]), "+f"((d)[3]) \
                 : "r"((a)[0]), "r"((a)[1]), "r"((a)[2]), "r"((a)[3]), \
                   "r"(b0), "r"(b1))

// QK kernel tile params (128x128, BK=64)
#define SROW 72
#define MATS (128 * SROW)

// 128x64 BK=32 GEMM params
#define SROW2 40                         // 32 halves + 8 pad
#define A_MAT (128 * SROW2)              // halves
#define B_MAT (64 * SROW2)
#define STAGEH (2 * A_MAT + 2 * B_MAT)   // halves per stage (Ah,Al,Bh,Bl)
#define SMEM64 (2 * STAGEH * 2)          // bytes (61440)

// ---------------------------------------------------------------------------
// fp32 -> fp16 hi/lo conversion (lo skipped for Wq/Wk)
// ---------------------------------------------------------------------------
__global__ __launch_bounds__(256) void convert_all(
    const float* __restrict__ x,  const float* __restrict__ wq,
    const float* __restrict__ wk, const float* __restrict__ wv,
    const float* __restrict__ wo)
{
    int t = blockIdx.x * 256 + threadIdx.x;       // float4 index, 786432 total
    const float* src;
    __half *dh, *dl;
    int idx;
    bool wantLo = true;
    if (t < 524288)      { src = x;  dh = g_xh;          dl = g_xl;          idx = t; }
    else if (t < 589824) { src = wq; dh = g_wh;          dl = g_wl;          idx = t - 524288; wantLo = false; }
    else if (t < 655360) { src = wk; dh = g_wh + 262144; dl = g_wl + 262144; idx = t - 589824; wantLo = false; }
    else if (t < 720896) { src = wv; dh = g_wh + 524288; dl = g_wl + 524288; idx = t - 655360; }
    else                 { src = wo; dh = g_oh;          dl = g_ol;          idx = t - 720896; }

    float4 v = ((const float4*)src)[idx];
    __half h0 = __float2half_rn(v.x), h1 = __float2half_rn(v.y);
    __half h2 = __float2half_rn(v.z), h3 = __float2half_rn(v.w);
    __half2* ph = (__half2*)(dh + idx * 4);
    ph[0] = __halves2half2(h0, h1); ph[1] = __halves2half2(h2, h3);
    if (wantLo) {
        __half l0 = __float2half_rn(v.x - __half2float(h0));
        __half l1 = __float2half_rn(v.y - __half2float(h1));
        __half l2 = __float2half_rn(v.z - __half2float(h2));
        __half l3 = __float2half_rn(v.w - __half2float(h3));
        __half2* pl = (__half2*)(dl + idx * 4);
        pl[0] = __halves2half2(l0, l1); pl[1] = __halves2half2(l2, l3);
    }
}

// ---------------------------------------------------------------------------
// Fused QK-diagonal GEMM (as R6): s[m,h] = Qrow.Krow in-register, writes sa/sc
// ---------------------------------------------------------------------------
__global__ __launch_bounds__(256) void gemm_qk_diag(
    const __half* __restrict__ Ah,
    const __half* __restrict__ Wq,
    const __half* __restrict__ Wk)
{
    constexpr uint32_t BUFB = 3u * MATS * 2;

    extern __shared__ __half sm[];
    const uint32_t sb = smem_u32(sm);
    const int tid = threadIdx.x;
    const int lane = tid & 31, wid = tid >> 5;
    const int wm = wid & 3, wn = wid >> 2;
    const int n0 = blockIdx.x * 128, m0 = blockIdx.y * 128;

    const int lr = tid >> 1, lp = tid & 1;
    const __half* gA = Ah + (size_t)(m0 + lr) * 512 + lp * 32;
    const __half* gQ = Wq + (size_t)(n0 + lr) * 512 + lp * 32;
    const __half* gK = Wk + (size_t)(n0 + lr) * 512 + lp * 32;
    const uint32_t dst0 = sb + (uint32_t)(lr * SROW + lp * 32) * 2;

#define LOADCHUNK_QK(c, b) { \
        const uint32_t d = dst0 + (uint32_t)(b) * BUFB; \
        const int ko = (c) * 64; \
        _Pragma("unroll") \
        for (int j = 0; j < 4; j++) { \
            CPASYNC(d + 0 * MATS * 2 + j * 16, gA + ko + j * 8); \
            CPASYNC(d + 1 * MATS * 2 + j * 16, gQ + ko + j * 8); \
            CPASYNC(d + 2 * MATS * 2 + j * 16, gK + ko + j * 8); \
        } }

    float aq[2][8][4], ak[2][8][4];
#pragma unroll
    for (int i = 0; i < 2; i++)
#pragma unroll
        for (int j = 0; j < 8; j++)
#pragma unroll
            for (int k = 0; k < 4; k++) { aq[i][j][k] = 0.0f; ak[i][j][k] = 0.0f; }

    LOADCHUNK_QK(0, 0);
    asm volatile("cp.async.commit_group;" ::: "memory");

    const uint32_t a_row_off =
        (uint32_t)((wm * 32 + (lane & 15)) * SROW) * 2 + (uint32_t)((lane >> 4) * 16);
    const int bn = wn * 64 + (lane & 7) + ((lane >> 4) << 3);
    const uint32_t b_row_off =
        (uint32_t)(bn * SROW) * 2 + (uint32_t)(((lane >> 3) & 1) * 16);

    for (int c = 0; c < 8; c++) {
        if (c < 7) {
            LOADCHUNK_QK(c + 1, (c + 1) & 1);
            asm volatile("cp.async.commit_group;" ::: "memory");
            asm volatile("cp.async.wait_group 1;" ::: "memory");
        } else {
            asm volatile("cp.async.wait_group 0;" ::: "memory");
        }
        __syncthreads();

        const uint32_t base = sb + (uint32_t)(c & 1) * BUFB;
#pragma unroll
        for (int kk = 0; kk < 4; kk++) {
            const uint32_t aA = base + a_row_off + kk * 32;
            uint32_t a0[4], a1[4];
            LDSM4(a0, aA);
            LDSM4(a1, aA + 16 * SROW * 2);

            const uint32_t bQ = base + 1 * MATS * 2 + b_row_off + kk * 32;
            const uint32_t bK = base + 2 * MATS * 2 + b_row_off + kk * 32;
#pragma unroll
            for (int jp = 0; jp < 4; jp++) {
                uint32_t bq[4], bk[4];
                LDSM4(bq, bQ + jp * 16 * SROW * 2);
                LDSM4(bk, bK + jp * 16 * SROW * 2);
                MMA(aq[0][2 * jp],     a0, bq[0], bq[1]);
                MMA(aq[1][2 * jp],     a1, bq[0], bq[1]);
                MMA(aq[0][2 * jp + 1], a0, bq[2], bq[3]);
                MMA(aq[1][2 * jp + 1], a1, bq[2], bq[3]);
                MMA(ak[0][2 * jp],     a0, bk[0], bk[1]);
                MMA(ak[1][2 * jp],     a1, bk[0], bk[1]);
                MMA(ak[0][2 * jp + 1], a0, bk[2], bk[3]);
                MMA(ak[1][2 * jp + 1], a1, bk[2], bk[3]);
            }
        }
        __syncthreads();
    }

    const int h = blockIdx.x * 2 + wn;
#pragma unroll
    for (int j = 0; j < 4; j++) {
        const int mi = j >> 1, o = (j & 1) * 2;
        float p = 0.0f;
#pragma unroll
        for (int ni = 0; ni < 8; ni++)
            p += aq[mi][ni][o] * ak[mi][ni][o]
               + aq[mi][ni][o + 1] * ak[mi][ni][o + 1];
        p += __shfl_xor_sync(0xFFFFFFFF, p, 1);
        p += __shfl_xor_sync(0xFFFFFFFF, p, 2);
        if ((lane & 3) == 0) {
            const int m = m0 + wm * 32 + (lane >> 2) + (j >> 1) * 16 + (j & 1) * 8;
            const int b = m >> 11, q = m & 2047;
            float sd = p * 0.125f;
            int cnt = SEQ - 1 - q;
            float mx = (cnt > 0) ? fmaxf(sd, 0.0f) : sd;
            float ed = expf(sd - mx);
            float eo = (cnt > 0) ? expf(-mx) : 0.0f;
            float Z = ed + (float)cnt * eo;
            g_sa[(b * 8 + h) * SEQ + q] = ed / Z;
            g_sc[(b * 8 + h) * SEQ + q] = eo / Z;
        }
    }
}

// ---------------------------------------------------------------------------
// fp16x3 GEMM, CTA tile 128x64, BK=32, double-buffered, 2 CTAs/SM.
// MODE 0: C += fp32 store (output projection)
// MODE 1: V epilogue — vh/vl fp16 hi/lo store + fused 32-row chunk sums
// ---------------------------------------------------------------------------
template<int MODE>
__global__ __launch_bounds__(256, 2) void gemm64(
    const __half* __restrict__ Ah, const __half* __restrict__ Al,
    const __half* __restrict__ Bh, const __half* __restrict__ Bl,
    float* __restrict__ C)
{
    extern __shared__ __half sm[];
    const uint32_t sb = smem_u32(sm);
    const int tid = threadIdx.x;
    const int lane = tid & 31, wid = tid >> 5;
    const int wm = wid & 3, wn = wid >> 2;
    const int n0 = blockIdx.x * 64, m0 = blockIdx.y * 128;

    // Load assignment
    const int lrA = tid >> 1;              // 0..127
    const int lpA = tid & 1;               // k-half (16 halves)
    const int lrB = tid >> 2;              // 0..63
    const int lpB = tid & 3;               // k-quarter (8 halves)
    const __half* gAh = Ah + (size_t)(m0 + lrA) * 512 + lpA * 16;
    const __half* gAl = Al + (size_t)(m0 + lrA) * 512 + lpA * 16;
    const __half* gBh = Bh + (size_t)(n0 + lrB) * 512 + lpB * 8;
    const __half* gBl = Bl + (size_t)(n0 + lrB) * 512 + lpB * 8;
    const uint32_t dA = sb + (uint32_t)(lrA * SROW2 + lpA * 16) * 2;
    const uint32_t dB = sb + (uint32_t)(lrB * SROW2 + lpB * 8) * 2;

#define LOADCH64(c, bsel) { \
        const uint32_t soff = (uint32_t)(bsel) * (STAGEH * 2); \
        const int ko = (c) * 32; \
        CPASYNC(dA + soff + 0 * A_MAT * 2 + 0,  gAh + ko); \
        CPASYNC(dA + soff + 0 * A_MAT * 2 + 16, gAh + ko + 8); \
        CPASYNC(dA + soff + 1 * A_MAT * 2 + 0,  gAl + ko); \
        CPASYNC(dA + soff + 1 * A_MAT * 2 + 16, gAl + ko + 8); \
        CPASYNC(dB + soff + 2 * A_MAT * 2 + 0,  gBh + ko); \
        CPASYNC(dB + soff + 2 * A_MAT * 2 + B_MAT * 2, gBl + ko); \
    }

    float acc[2][4][4];
#pragma unroll
    for (int i = 0; i < 2; i++)
#pragma unroll
        for (int j = 0; j < 4; j++)
#pragma unroll
            for (int k = 0; k < 4; k++) acc[i][j][k] = 0.0f;

    LOADCH64(0, 0);
    asm volatile("cp.async.commit_group;" ::: "memory");

    const uint32_t a_row_off =
        (uint32_t)((wm * 32 + (lane & 15)) * SROW2) * 2 + (uint32_t)((lane >> 4) * 16);
    const int bn = wn * 32 + (lane & 7) + ((lane >> 4) << 3);
    const uint32_t b_row_off =
        (uint32_t)(bn * SROW2) * 2 + (uint32_t)(((lane >> 3) & 1) * 16);

    for (int c = 0; c < 16; c++) {
        if (c < 15) {
            LOADCH64(c + 1, (c + 1) & 1);
            asm volatile("cp.async.commit_group;" ::: "memory");
            asm volatile("cp.async.wait_group 1;" ::: "memory");
        } else {
            asm volatile("cp.async.wait_group 0;" ::: "memory");
        }
        __syncthreads();

        const uint32_t base = sb + (uint32_t)(c & 1) * (STAGEH * 2);
#pragma unroll
        for (int kk = 0; kk < 2; kk++) {
            const uint32_t aH = base + a_row_off + kk * 32;
            const uint32_t aL = aH + A_MAT * 2;
            uint32_t ah0[4], ah1[4], al0[4], al1[4];
            LDSM4(ah0, aH);
            LDSM4(ah1, aH + 16 * SROW2 * 2);
            LDSM4(al0, aL);
            LDSM4(al1, aL + 16 * SROW2 * 2);

            const uint32_t bH = base + 2 * A_MAT * 2 + b_row_off + kk * 32;
            const uint32_t bL = bH + B_MAT * 2;
#pragma unroll
            for (int jp = 0; jp < 2; jp++) {
                uint32_t bh[4], bl[4];
                LDSM4(bh, bH + jp * 16 * SROW2 * 2);
                LDSM4(bl, bL + jp * 16 * SROW2 * 2);
                MMA(acc[0][2 * jp],     ah0, bh[0], bh[1]);
                MMA(acc[1][2 * jp],     ah1, bh[0], bh[1]);
                MMA(acc[0][2 * jp + 1], ah0, bh[2], bh[3]);
                MMA(acc[1][2 * jp + 1], ah1, bh[2], bh[3]);
                MMA(acc[0][2 * jp],     al0, bh[0], bh[1]);
                MMA(acc[1][2 * jp],     al1, bh[0], bh[1]);
                MMA(acc[0][2 * jp + 1], al0, bh[2], bh[3]);
                MMA(acc[1][2 * jp + 1], al1, bh[2], bh[3]);
                MMA(acc[0][2 * jp],     ah0, bl[0], bl[1]);
                MMA(acc[1][2 * jp],     ah1, bl[0], bl[1]);
                MMA(acc[0][2 * jp + 1], ah0, bl[2], bl[3]);
                MMA(acc[1][2 * jp + 1], ah1, bl[2], bl[3]);
            }
        }
        __syncthreads();
    }

    const int r0 = m0 + wm * 32 + (lane >> 2);
    const int cb = n0 + wn * 32 + (lane & 3) * 2;

    if (MODE == 0) {
#pragma unroll
        for (int mi = 0; mi < 2; mi++) {
            const int r = r0 + mi * 16;
#pragma unroll
            for (int ni = 0; ni < 4; ni++) {
                const int cg = cb + ni * 8;
                *(float2*)&C[(size_t)r * 512 + cg] =
                    make_float2(acc[mi][ni][0], acc[mi][ni][1]);
                *(float2*)&C[(size_t)(r + 8) * 512 + cg] =
                    make_float2(acc[mi][ni][2], acc[mi][ni][3]);
            }
        }
    } else {
        // V epilogue: fp16 hi/lo store
#pragma unroll
        for (int mi = 0; mi < 2; mi++) {
#pragma unroll
            for (int ni = 0; ni < 4; ni++) {
                const int cg = cb + ni * 8;
#pragma unroll
                for (int rr = 0; rr < 2; rr++) {
                    const int r = r0 + mi * 16 + rr * 8;
                    float v0 = acc[mi][ni][rr * 2], v1 = acc[mi][ni][rr * 2 + 1];
                    __half h0 = __float2half_rn(v0), h1 = __float2half_rn(v1);
                    __half l0 = __float2half_rn(v0 - __half2float(h0));
                    __half l1 = __float2half_rn(v1 - __half2float(h1));
                    *(__half2*)&g_vh[(size_t)r * 512 + cg] = __halves2half2(h0, h1);
                    *(__half2*)&g_vl[(size_t)r * 512 + cg] = __halves2half2(l0, l1);
                }
            }
        }
        // Fused 32-row chunk sums: warp rows = one chunk, warp cols = half a head
        const int b = m0 >> 11;
        const int chunk = ((m0 & 2047) >> 5) + wm;
        const int h = n0 >> 6;
        float* csbase = g_cs + ((size_t)(b * 8 + h) * 64 + chunk) * 64;
#pragma unroll
        for (int ni = 0; ni < 4; ni++) {
            float s0 = acc[0][ni][0] + acc[0][ni][2] + acc[1][ni][0] + acc[1][ni][2];
            float s1 = acc[0][ni][1] + acc[0][ni][3] + acc[1][ni][1] + acc[1][ni][3];
#pragma unroll
            for (int st = 4; st < 32; st <<= 1) {
                s0 += __shfl_xor_sync(0xFFFFFFFF, s0, st);
                s1 += __shfl_xor_sync(0xFFFFFFFF, s1, st);
            }
            if (lane < 4) {
                const int dh = wn * 32 + (lane << 1) + ni * 8;
                *(float2*)&csbase[dh] = make_float2(s0, s1);
            }
        }
    }
}

// ---------------------------------------------------------------------------
// Scan: z[q] = a_q*v[q] + c_q*suffix_{p>q} v[p]
// ---------------------------------------------------------------------------
__global__ __launch_bounds__(256) void v_scan()
{
    int bh = blockIdx.y;
    int chunk = blockIdx.x * 4 + (threadIdx.x >> 6);
    int dh = threadIdx.x & 63;
    int b = bh >> 3, h = bh & 7;

    float run = 0.0f;
    const float* cs = g_cs + (size_t)bh * 64 * 64 + dh;
    for (int c2 = chunk + 1; c2 < 64; c2++)
        run += cs[(size_t)c2 * 64];

    const float* sa = g_sa + bh * SEQ;
    const float* sc = g_sc + bh * SEQ;
    const int q0 = chunk * 32;
#pragma unroll 4
    for (int i = 31; i >= 0; i--) {
        int q = q0 + i;
        size_t row = (size_t)(b * SEQ + q) * DMODEL + h * DH + dh;
        float v = __half2float(g_vh[row]) + __half2float(g_vl[row]);
        float z = sa[q] * v + sc[q] * run;
        __half zh = __float2half_rn(z);
        g_zh[row] = zh;
        g_zl[row] = __float2half_rn(z - __half2float(zh));
        run += v;
    }
}

// ---------------------------------------------------------------------------
extern "C" void kernel_launch(void* const* d_in, const int* in_sizes, int n_in,
                              void* d_out, int out_size)
{
    const float* x  = (const float*)d_in[0];
    const float* WQ = (const float*)d_in[1];
    const float* WK = (const float*)d_in[2];
    const float* WV = (const float*)d_in[3];
    const float* WO = (const float*)d_in[4];
    float* out = (float*)d_out;

    const int SMEMQK = 2 * 3 * MATS * 2;   // 110592 B
    cudaFuncSetAttribute(gemm_qk_diag, cudaFuncAttributeMaxDynamicSharedMemorySize,
                         SMEMQK);
    cudaFuncSetAttribute(gemm64<0>, cudaFuncAttributeMaxDynamicSharedMemorySize,
                         SMEM64);
    cudaFuncSetAttribute(gemm64<1>, cudaFuncAttributeMaxDynamicSharedMemorySize,
                         SMEM64);

    __half *xh, *xl, *wh, *wl, *oh, *ol, *zh, *zl;
    cudaGetSymbolAddress((void**)&xh, g_xh);
    cudaGetSymbolAddress((void**)&xl, g_xl);
    cudaGetSymbolAddress((void**)&wh, g_wh);
    cudaGetSymbolAddress((void**)&wl, g_wl);
    cudaGetSymbolAddress((void**)&oh, g_oh);
    cudaGetSymbolAddress((void**)&ol, g_ol);
    cudaGetSymbolAddress((void**)&zh, g_zh);
    cudaGetSymbolAddress((void**)&zl, g_zl);

    convert_all<<<3072, 256>>>(x, WQ, WK, WV, WO);

    // QK-diag: writes g_sa/g_sc directly
    gemm_qk_diag<<<dim3(4, 32), 256, SMEMQK>>>(xh, wh, wh + 512 * 512);

    // V projection (fp16x3) with fused chunk sums + hi/lo store
    gemm64<1><<<dim3(8, 32), 256, SMEM64>>>(
        xh, xl, wh + 1024 * 512, wl + 1024 * 512, out /*unused*/);

    v_scan<<<dim3(16, 16), 256>>>();

    // Output projection (fp16x3)
    gemm64<0><<<dim3(8, 32), 256, SMEM64>>>(zh, zl, oh, ol, out);
}

// round 9
// speedup vs baseline: 1.1254x; 1.0676x over previous
#include <cuda_runtime.h>
#include <cuda_fp16.h>
#include <math.h>
#include <stdint.h>

#define SEQ     2048
#define DMODEL  512
#define NH      8
#define DH      64
#define BATCH   2
#define MTOT    4096

// ---------------- scratch (__device__ globals, allocation-free) -------------
__device__ __half g_xh[MTOT * DMODEL];
__device__ __half g_xl[MTOT * DMODEL];
__device__ __half g_wh[3 * DMODEL * DMODEL];   // [Wq;Wk;Wv] rows 0..1535 (hi)
__device__ __half g_wl[3 * DMODEL * DMODEL];   // lo used only for Wv range
__device__ __half g_oh[DMODEL * DMODEL];
__device__ __half g_ol[DMODEL * DMODEL];
__device__ float  g_V [MTOT * DMODEL];
__device__ __half g_zh[MTOT * DMODEL];
__device__ __half g_zl[MTOT * DMODEL];
__device__ float  g_sa[16 * SEQ];
__device__ float  g_sc[16 * SEQ];
__device__ float  g_cs[16 * 64 * 64];   // per-(bh, chunk32, dh) V column sums

// ---------------------------------------------------------------------------
__device__ __forceinline__ uint32_t smem_u32(const void* p) {
    uint32_t a;
    asm("{ .reg .u64 t; cvta.to.shared.u64 t, %1; cvt.u32.u64 %0, t; }"
        : "=r"(a) : "l"(p));
    return a;
}

#define CPASYNC(d, s) \
    asm volatile("cp.async.cg.shared.global [%0], [%1], 16;" \
                 :: "r"(d), "l"(s) : "memory")

#define LDSM4(r, a) \
    asm volatile("ldmatrix.sync.aligned.m8n8.x4.shared.b16 {%0,%1,%2,%3}, [%4];" \
                 : "=r"((r)[0]), "=r"((r)[1]), "=r"((r)[2]), "=r"((r)[3]) \
                 : "r"(a))

#define MMA(d, a, b0, b1) \
    asm volatile("mma.sync.aligned.m16n8k16.row.col.f32.f16.f16.f32 " \
                 "{%0,%1,%2,%3},{%4,%5,%6,%7},{%8,%9},{%0,%1,%2,%3};" \
                 : "+f"((d)[0]), "+f"((d)[1]), "+f"((d)[2]), "+f"((d)[3]) \
                 : "r"((a)[0]), "r"((a)[1]), "r"((a)[2]), "r"((a)[3]), \
                   "r"(b0), "r"(b1))

// QK kernel tile params (128x128, BK=64)
#define SROW 72
#define MATS (128 * SROW)

// 128x64 BK=32 GEMM params
#define SROW2 40                         // 32 halves + 8 pad
#define A_MAT (128 * SROW2)              // halves
#define B_MAT (64 * SROW2)
#define STAGEH (2 * A_MAT + 2 * B_MAT)   // halves per stage (Ah,Al,Bh,Bl)
#define SMEM64 (2 * STAGEH * 2)          // bytes (61440)

// ---------------------------------------------------------------------------
// fp32 -> fp16 hi/lo conversion (lo skipped for Wq/Wk)
// ---------------------------------------------------------------------------
__global__ __launch_bounds__(256) void convert_all(
    const float* __restrict__ x,  const float* __restrict__ wq,
    const float* __restrict__ wk, const float* __restrict__ wv,
    const float* __restrict__ wo)
{
    int t = blockIdx.x * 256 + threadIdx.x;       // float4 index, 786432 total
    const float* src;
    __half *dh, *dl;
    int idx;
    bool wantLo = true;
    if (t < 524288)      { src = x;  dh = g_xh;          dl = g_xl;          idx = t; }
    else if (t < 589824) { src = wq; dh = g_wh;          dl = g_wl;          idx = t - 524288; wantLo = false; }
    else if (t < 655360) { src = wk; dh = g_wh + 262144; dl = g_wl + 262144; idx = t - 589824; wantLo = false; }
    else if (t < 720896) { src = wv; dh = g_wh + 524288; dl = g_wl + 524288; idx = t - 655360; }
    else                 { src = wo; dh = g_oh;          dl = g_ol;          idx = t - 720896; }

    float4 v = ((const float4*)src)[idx];
    __half h0 = __float2half_rn(v.x), h1 = __float2half_rn(v.y);
    __half h2 = __float2half_rn(v.z), h3 = __float2half_rn(v.w);
    __half2* ph = (__half2*)(dh + idx * 4);
    ph[0] = __halves2half2(h0, h1); ph[1] = __halves2half2(h2, h3);
    if (wantLo) {
        __half l0 = __float2half_rn(v.x - __half2float(h0));
        __half l1 = __float2half_rn(v.y - __half2float(h1));
        __half l2 = __float2half_rn(v.z - __half2float(h2));
        __half l3 = __float2half_rn(v.w - __half2float(h3));
        __half2* pl = (__half2*)(dl + idx * 4);
        pl[0] = __halves2half2(l0, l1); pl[1] = __halves2half2(l2, l3);
    }
}

// ---------------------------------------------------------------------------
// Fused QK-diagonal GEMM: s[m,h] = Qrow.Krow in-register, writes sa/sc
// ---------------------------------------------------------------------------
__global__ __launch_bounds__(256) void gemm_qk_diag(
    const __half* __restrict__ Ah,
    const __half* __restrict__ Wq,
    const __half* __restrict__ Wk)
{
    constexpr uint32_t BUFB = 3u * MATS * 2;

    extern __shared__ __half sm[];
    const uint32_t sb = smem_u32(sm);
    const int tid = threadIdx.x;
    const int lane = tid & 31, wid = tid >> 5;
    const int wm = wid & 3, wn = wid >> 2;
    const int n0 = blockIdx.x * 128, m0 = blockIdx.y * 128;

    const int lr = tid >> 1, lp = tid & 1;
    const __half* gA = Ah + (size_t)(m0 + lr) * 512 + lp * 32;
    const __half* gQ = Wq + (size_t)(n0 + lr) * 512 + lp * 32;
    const __half* gK = Wk + (size_t)(n0 + lr) * 512 + lp * 32;
    const uint32_t dst0 = sb + (uint32_t)(lr * SROW + lp * 32) * 2;

#define LOADCHUNK_QK(c, b) { \
        const uint32_t d = dst0 + (uint32_t)(b) * BUFB; \
        const int ko = (c) * 64; \
        _Pragma("unroll") \
        for (int j = 0; j < 4; j++) { \
            CPASYNC(d + 0 * MATS * 2 + j * 16, gA + ko + j * 8); \
            CPASYNC(d + 1 * MATS * 2 + j * 16, gQ + ko + j * 8); \
            CPASYNC(d + 2 * MATS * 2 + j * 16, gK + ko + j * 8); \
        } }

    float aq[2][8][4], ak[2][8][4];
#pragma unroll
    for (int i = 0; i < 2; i++)
#pragma unroll
        for (int j = 0; j < 8; j++)
#pragma unroll
            for (int k = 0; k < 4; k++) { aq[i][j][k] = 0.0f; ak[i][j][k] = 0.0f; }

    LOADCHUNK_QK(0, 0);
    asm volatile("cp.async.commit_group;" ::: "memory");

    const uint32_t a_row_off =
        (uint32_t)((wm * 32 + (lane & 15)) * SROW) * 2 + (uint32_t)((lane >> 4) * 16);
    const int bn = wn * 64 + (lane & 7) + ((lane >> 4) << 3);
    const uint32_t b_row_off =
        (uint32_t)(bn * SROW) * 2 + (uint32_t)(((lane >> 3) & 1) * 16);

    for (int c = 0; c < 8; c++) {
        if (c < 7) {
            LOADCHUNK_QK(c + 1, (c + 1) & 1);
            asm volatile("cp.async.commit_group;" ::: "memory");
            asm volatile("cp.async.wait_group 1;" ::: "memory");
        } else {
            asm volatile("cp.async.wait_group 0;" ::: "memory");
        }
        __syncthreads();

        const uint32_t base = sb + (uint32_t)(c & 1) * BUFB;
#pragma unroll
        for (int kk = 0; kk < 4; kk++) {
            const uint32_t aA = base + a_row_off + kk * 32;
            uint32_t a0[4], a1[4];
            LDSM4(a0, aA);
            LDSM4(a1, aA + 16 * SROW * 2);

            const uint32_t bQ = base + 1 * MATS * 2 + b_row_off + kk * 32;
            const uint32_t bK = base + 2 * MATS * 2 + b_row_off + kk * 32;
#pragma unroll
            for (int jp = 0; jp < 4; jp++) {
                uint32_t bq[4], bk[4];
                LDSM4(bq, bQ + jp * 16 * SROW * 2);
                LDSM4(bk, bK + jp * 16 * SROW * 2);
                MMA(aq[0][2 * jp],     a0, bq[0], bq[1]);
                MMA(aq[1][2 * jp],     a1, bq[0], bq[1]);
                MMA(aq[0][2 * jp + 1], a0, bq[2], bq[3]);
                MMA(aq[1][2 * jp + 1], a1, bq[2], bq[3]);
                MMA(ak[0][2 * jp],     a0, bk[0], bk[1]);
                MMA(ak[1][2 * jp],     a1, bk[0], bk[1]);
                MMA(ak[0][2 * jp + 1], a0, bk[2], bk[3]);
                MMA(ak[1][2 * jp + 1], a1, bk[2], bk[3]);
            }
        }
        __syncthreads();
    }

    const int h = blockIdx.x * 2 + wn;
#pragma unroll
    for (int j = 0; j < 4; j++) {
        const int mi = j >> 1, o = (j & 1) * 2;
        float p = 0.0f;
#pragma unroll
        for (int ni = 0; ni < 8; ni++)
            p += aq[mi][ni][o] * ak[mi][ni][o]
               + aq[mi][ni][o + 1] * ak[mi][ni][o + 1];
        p += __shfl_xor_sync(0xFFFFFFFF, p, 1);
        p += __shfl_xor_sync(0xFFFFFFFF, p, 2);
        if ((lane & 3) == 0) {
            const int m = m0 + wm * 32 + (lane >> 2) + (j >> 1) * 16 + (j & 1) * 8;
            const int b = m >> 11, q = m & 2047;
            float sd = p * 0.125f;
            int cnt = SEQ - 1 - q;
            float mx = (cnt > 0) ? fmaxf(sd, 0.0f) : sd;
            float ed = expf(sd - mx);
            float eo = (cnt > 0) ? expf(-mx) : 0.0f;
            float Z = ed + (float)cnt * eo;
            g_sa[(b * 8 + h) * SEQ + q] = ed / Z;
            g_sc[(b * 8 + h) * SEQ + q] = eo / Z;
        }
    }
}

// ---------------------------------------------------------------------------
// fp16x3 GEMM, CTA tile 128x64, BK=32, double-buffered, 2 CTAs/SM.
// MODE 0: fp32 store (output projection)
// MODE 1: fp32 store into C + fused 32-row chunk sums (V projection)
// ---------------------------------------------------------------------------
template<int MODE>
__global__ __launch_bounds__(256, 2) void gemm64(
    const __half* __restrict__ Ah, const __half* __restrict__ Al,
    const __half* __restrict__ Bh, const __half* __restrict__ Bl,
    float* __restrict__ C)
{
    extern __shared__ __half sm[];
    const uint32_t sb = smem_u32(sm);
    const int tid = threadIdx.x;
    const int lane = tid & 31, wid = tid >> 5;
    const int wm = wid & 3, wn = wid >> 2;
    const int n0 = blockIdx.x * 64, m0 = blockIdx.y * 128;

    const int lrA = tid >> 1;
    const int lpA = tid & 1;
    const int lrB = tid >> 2;
    const int lpB = tid & 3;
    const __half* gAh = Ah + (size_t)(m0 + lrA) * 512 + lpA * 16;
    const __half* gAl = Al + (size_t)(m0 + lrA) * 512 + lpA * 16;
    const __half* gBh = Bh + (size_t)(n0 + lrB) * 512 + lpB * 8;
    const __half* gBl = Bl + (size_t)(n0 + lrB) * 512 + lpB * 8;
    const uint32_t dA = sb + (uint32_t)(lrA * SROW2 + lpA * 16) * 2;
    const uint32_t dB = sb + (uint32_t)(lrB * SROW2 + lpB * 8) * 2;

#define LOADCH64(c, bsel) { \
        const uint32_t soff = (uint32_t)(bsel) * (STAGEH * 2); \
        const int ko = (c) * 32; \
        CPASYNC(dA + soff + 0 * A_MAT * 2 + 0,  gAh + ko); \
        CPASYNC(dA + soff + 0 * A_MAT * 2 + 16, gAh + ko + 8); \
        CPASYNC(dA + soff + 1 * A_MAT * 2 + 0,  gAl + ko); \
        CPASYNC(dA + soff + 1 * A_MAT * 2 + 16, gAl + ko + 8); \
        CPASYNC(dB + soff + 2 * A_MAT * 2 + 0,  gBh + ko); \
        CPASYNC(dB + soff + 2 * A_MAT * 2 + B_MAT * 2, gBl + ko); \
    }

    float acc[2][4][4];
#pragma unroll
    for (int i = 0; i < 2; i++)
#pragma unroll
        for (int j = 0; j < 4; j++)
#pragma unroll
            for (int k = 0; k < 4; k++) acc[i][j][k] = 0.0f;

    LOADCH64(0, 0);
    asm volatile("cp.async.commit_group;" ::: "memory");

    const uint32_t a_row_off =
        (uint32_t)((wm * 32 + (lane & 15)) * SROW2) * 2 + (uint32_t)((lane >> 4) * 16);
    const int bn = wn * 32 + (lane & 7) + ((lane >> 4) << 3);
    const uint32_t b_row_off =
        (uint32_t)(bn * SROW2) * 2 + (uint32_t)(((lane >> 3) & 1) * 16);

    for (int c = 0; c < 16; c++) {
        if (c < 15) {
            LOADCH64(c + 1, (c + 1) & 1);
            asm volatile("cp.async.commit_group;" ::: "memory");
            asm volatile("cp.async.wait_group 1;" ::: "memory");
        } else {
            asm volatile("cp.async.wait_group 0;" ::: "memory");
        }
        __syncthreads();

        const uint32_t base = sb + (uint32_t)(c & 1) * (STAGEH * 2);
#pragma unroll
        for (int kk = 0; kk < 2; kk++) {
            const uint32_t aH = base + a_row_off + kk * 32;
            const uint32_t aL = aH + A_MAT * 2;
            uint32_t ah0[4], ah1[4], al0[4], al1[4];
            LDSM4(ah0, aH);
            LDSM4(ah1, aH + 16 * SROW2 * 2);
            LDSM4(al0, aL);
            LDSM4(al1, aL + 16 * SROW2 * 2);

            const uint32_t bH = base + 2 * A_MAT * 2 + b_row_off + kk * 32;
            const uint32_t bL = bH + B_MAT * 2;
#pragma unroll
            for (int jp = 0; jp < 2; jp++) {
                uint32_t bh[4], bl[4];
                LDSM4(bh, bH + jp * 16 * SROW2 * 2);
                LDSM4(bl, bL + jp * 16 * SROW2 * 2);
                MMA(acc[0][2 * jp],     ah0, bh[0], bh[1]);
                MMA(acc[1][2 * jp],     ah1, bh[0], bh[1]);
                MMA(acc[0][2 * jp + 1], ah0, bh[2], bh[3]);
                MMA(acc[1][2 * jp + 1], ah1, bh[2], bh[3]);
                MMA(acc[0][2 * jp],     al0, bh[0], bh[1]);
                MMA(acc[1][2 * jp],     al1, bh[0], bh[1]);
                MMA(acc[0][2 * jp + 1], al0, bh[2], bh[3]);
                MMA(acc[1][2 * jp + 1], al1, bh[2], bh[3]);
                MMA(acc[0][2 * jp],     ah0, bl[0], bl[1]);
                MMA(acc[1][2 * jp],     ah1, bl[0], bl[1]);
                MMA(acc[0][2 * jp + 1], ah0, bl[2], bl[3]);
                MMA(acc[1][2 * jp + 1], ah1, bl[2], bl[3]);
            }
        }
        __syncthreads();
    }

    const int r0 = m0 + wm * 32 + (lane >> 2);
    const int cb = n0 + wn * 32 + (lane & 3) * 2;

    // fp32 store (both modes)
#pragma unroll
    for (int mi = 0; mi < 2; mi++) {
        const int r = r0 + mi * 16;
#pragma unroll
        for (int ni = 0; ni < 4; ni++) {
            const int cg = cb + ni * 8;
            *(float2*)&C[(size_t)r * 512 + cg] =
                make_float2(acc[mi][ni][0], acc[mi][ni][1]);
            *(float2*)&C[(size_t)(r + 8) * 512 + cg] =
                make_float2(acc[mi][ni][2], acc[mi][ni][3]);
        }
    }

    if (MODE == 1) {
        // Fused 32-row chunk sums: warp rows = one chunk, warp cols = half a head
        const int b = m0 >> 11;
        const int chunk = ((m0 & 2047) >> 5) + wm;
        const int h = n0 >> 6;
        float* csbase = g_cs + ((size_t)(b * 8 + h) * 64 + chunk) * 64;
#pragma unroll
        for (int ni = 0; ni < 4; ni++) {
            float s0 = acc[0][ni][0] + acc[0][ni][2] + acc[1][ni][0] + acc[1][ni][2];
            float s1 = acc[0][ni][1] + acc[0][ni][3] + acc[1][ni][1] + acc[1][ni][3];
#pragma unroll
            for (int st = 4; st < 32; st <<= 1) {
                s0 += __shfl_xor_sync(0xFFFFFFFF, s0, st);
                s1 += __shfl_xor_sync(0xFFFFFFFF, s1, st);
            }
            if (lane < 4) {
                const int dh = wn * 32 + (lane << 1) + ni * 8;
                *(float2*)&csbase[dh] = make_float2(s0, s1);
            }
        }
    }
}

// ---------------------------------------------------------------------------
// Scan: z[q] = a_q*v[q] + c_q*suffix_{p>q} v[p]   (fp32 V read, hi/lo z store)
// ---------------------------------------------------------------------------
__global__ __launch_bounds__(256) void v_scan()
{
    int bh = blockIdx.y;
    int chunk = blockIdx.x * 4 + (threadIdx.x >> 6);
    int dh = threadIdx.x & 63;
    int b = bh >> 3, h = bh & 7;

    float run = 0.0f;
    const float* cs = g_cs + (size_t)bh * 64 * 64 + dh;
    for (int c2 = chunk + 1; c2 < 64; c2++)
        run += cs[(size_t)c2 * 64];

    const float* sa = g_sa + bh * SEQ;
    const float* sc = g_sc + bh * SEQ;
    const int q0 = chunk * 32;
#pragma unroll 4
    for (int i = 31; i >= 0; i--) {
        int q = q0 + i;
        size_t row = (size_t)(b * SEQ + q) * DMODEL + h * DH + dh;
        float v = g_V[row];
        float z = sa[q] * v + sc[q] * run;
        __half zh = __float2half_rn(z);
        g_zh[row] = zh;
        g_zl[row] = __float2half_rn(z - __half2float(zh));
        run += v;
    }
}

// ---------------------------------------------------------------------------
extern "C" void kernel_launch(void* const* d_in, const int* in_sizes, int n_in,
                              void* d_out, int out_size)
{
    const float* x  = (const float*)d_in[0];
    const float* WQ = (const float*)d_in[1];
    const float* WK = (const float*)d_in[2];
    const float* WV = (const float*)d_in[3];
    const float* WO = (const float*)d_in[4];
    float* out = (float*)d_out;

    const int SMEMQK = 2 * 3 * MATS * 2;   // 110592 B
    cudaFuncSetAttribute(gemm_qk_diag, cudaFuncAttributeMaxDynamicSharedMemorySize,
                         SMEMQK);
    cudaFuncSetAttribute(gemm64<0>, cudaFuncAttributeMaxDynamicSharedMemorySize,
                         SMEM64);
    cudaFuncSetAttribute(gemm64<1>, cudaFuncAttributeMaxDynamicSharedMemorySize,
                         SMEM64);

    __half *xh, *xl, *wh, *wl, *oh, *ol, *zh, *zl;
    float *gv;
    cudaGetSymbolAddress((void**)&xh, g_xh);
    cudaGetSymbolAddress((void**)&xl, g_xl);
    cudaGetSymbolAddress((void**)&wh, g_wh);
    cudaGetSymbolAddress((void**)&wl, g_wl);
    cudaGetSymbolAddress((void**)&oh, g_oh);
    cudaGetSymbolAddress((void**)&ol, g_ol);
    cudaGetSymbolAddress((void**)&zh, g_zh);
    cudaGetSymbolAddress((void**)&zl, g_zl);
    cudaGetSymbolAddress((void**)&gv, g_V);

    convert_all<<<3072, 256>>>(x, WQ, WK, WV, WO);

    // QK-diag: writes g_sa/g_sc directly
    gemm_qk_diag<<<dim3(4, 32), 256, SMEMQK>>>(xh, wh, wh + 512 * 512);

    // V projection (fp16x3), fp32 V store + fused chunk sums
    gemm64<1><<<dim3(8, 32), 256, SMEM64>>>(
        xh, xl, wh + 1024 * 512, wl + 1024 * 512, gv);

    v_scan<<<dim3(16, 16), 256>>>();

    // Output projection (fp16x3)
    gemm64<0><<<dim3(8, 32), 256, SMEM64>>>(zh, zl, oh, ol, out);
}

// round 10
// speedup vs baseline: 1.1729x; 1.0423x over previous
#include <cuda_runtime.h>
#include <cuda_fp16.h>
#include <math.h>
#include <stdint.h>

#define SEQ     2048
#define DMODEL  512
#define NH      8
#define DH      64
#define BATCH   2
#define MTOT    4096

// ---------------- scratch (__device__ globals, allocation-free) -------------
__device__ __half g_xh[MTOT * DMODEL];
__device__ __half g_xl[MTOT * DMODEL];
__device__ __half g_wh[3 * DMODEL * DMODEL];   // [Wq;Wk;Wv] rows 0..1535 (hi)
__device__ __half g_wl[3 * DMODEL * DMODEL];   // lo used only for Wv range
__device__ __half g_oh[DMODEL * DMODEL];
__device__ __half g_ol[DMODEL * DMODEL];
__device__ float  g_V [MTOT * DMODEL];
__device__ __half g_zh[MTOT * DMODEL];
__device__ __half g_zl[MTOT * DMODEL];
__device__ float  g_sa[16 * SEQ];
__device__ float  g_sc[16 * SEQ];
__device__ float  g_cs [16 * 128 * 64];  // per-(bh, chunk16, dh) V column sums
__device__ float  g_suf[16 * 128 * 64];  // suffix sums of g_cs over chunks

// ---------------------------------------------------------------------------
__device__ __forceinline__ uint32_t smem_u32(const void* p) {
    uint32_t a;
    asm("{ .reg .u64 t; cvta.to.shared.u64 t, %1; cvt.u32.u64 %0, t; }"
        : "=r"(a) : "l"(p));
    return a;
}

#define CPASYNC(d, s) \
    asm volatile("cp.async.cg.shared.global [%0], [%1], 16;" \
                 :: "r"(d), "l"(s) : "memory")

#define LDSM4(r, a) \
    asm volatile("ldmatrix.sync.aligned.m8n8.x4.shared.b16 {%0,%1,%2,%3}, [%4];" \
                 : "=r"((r)[0]), "=r"((r)[1]), "=r"((r)[2]), "=r"((r)[3]) \
                 : "r"(a))

#define MMA(d, a, b0, b1) \
    asm volatile("mma.sync.aligned.m16n8k16.row.col.f32.f16.f16.f32 " \
                 "{%0,%1,%2,%3},{%4,%5,%6,%7},{%8,%9},{%0,%1,%2,%3};" \
                 : "+f"((d)[0]), "+f"((d)[1]), "+f"((d)[2]), "+f"((d)[3]) \
                 : "r"((a)[0]), "r"((a)[1]), "r"((a)[2]), "r"((a)[3]), \
                   "r"(b0), "r"(b1))

// 128x64 BK=32 tiling
#define SROW2 40                         // 32 halves + 8 pad
#define A_MAT (128 * SROW2)              // halves
#define B_MAT (64 * SROW2)
#define STAGEH (2 * A_MAT + 2 * B_MAT)   // gemm64 stage (Ah,Al,Bh,Bl)
#define SMEM64 (2 * STAGEH * 2)          // 61440 B
#define STAGEQK (A_MAT + 2 * B_MAT)      // qk64 stage (A,BQ,BK)
#define SMEMQK64 (2 * STAGEQK * 2)       // 40960 B

// ---------------------------------------------------------------------------
// fp32 -> fp16 hi/lo conversion (lo skipped for Wq/Wk)
// ---------------------------------------------------------------------------
__global__ __launch_bounds__(256) void convert_all(
    const float* __restrict__ x,  const float* __restrict__ wq,
    const float* __restrict__ wk, const float* __restrict__ wv,
    const float* __restrict__ wo)
{
    int t = blockIdx.x * 256 + threadIdx.x;       // float4 index, 786432 total
    const float* src;
    __half *dh, *dl;
    int idx;
    bool wantLo = true;
    if (t < 524288)      { src = x;  dh = g_xh;          dl = g_xl;          idx = t; }
    else if (t < 589824) { src = wq; dh = g_wh;          dl = g_wl;          idx = t - 524288; wantLo = false; }
    else if (t < 655360) { src = wk; dh = g_wh + 262144; dl = g_wl + 262144; idx = t - 589824; wantLo = false; }
    else if (t < 720896) { src = wv; dh = g_wh + 524288; dl = g_wl + 524288; idx = t - 655360; }
    else                 { src = wo; dh = g_oh;          dl = g_ol;          idx = t - 720896; }

    float4 v = ((const float4*)src)[idx];
    __half h0 = __float2half_rn(v.x), h1 = __float2half_rn(v.y);
    __half h2 = __float2half_rn(v.z), h3 = __float2half_rn(v.w);
    __half2* ph = (__half2*)(dh + idx * 4);
    ph[0] = __halves2half2(h0, h1); ph[1] = __halves2half2(h2, h3);
    if (wantLo) {
        __half l0 = __float2half_rn(v.x - __half2float(h0));
        __half l1 = __float2half_rn(v.y - __half2float(h1));
        __half l2 = __float2half_rn(v.z - __half2float(h2));
        __half l3 = __float2half_rn(v.w - __half2float(h3));
        __half2* pl = (__half2*)(dl + idx * 4);
        pl[0] = __halves2half2(l0, l1); pl[1] = __halves2half2(l2, l3);
    }
}

// ---------------------------------------------------------------------------
// QK-diag, 128x64 tile, BK=32, 2 CTA/SM. One head per CTA (bx = head).
// Computes s[m,h] = Qrow.Krow via in-register partial dots + smem reduction.
// ---------------------------------------------------------------------------
__global__ __launch_bounds__(256, 2) void qk64(
    const __half* __restrict__ xh,
    const __half* __restrict__ Wq,
    const __half* __restrict__ Wk)
{
    extern __shared__ __half sm[];
    const uint32_t sb = smem_u32(sm);
    const int tid = threadIdx.x;
    const int lane = tid & 31, wid = tid >> 5;
    const int wm = wid & 3, wn = wid >> 2;
    const int n0 = blockIdx.x * 64, m0 = blockIdx.y * 128;

    const int lrA = tid >> 1, lpA = tid & 1;
    const int lrB = tid >> 2, lpB = tid & 3;
    const __half* gA = xh + (size_t)(m0 + lrA) * 512 + lpA * 16;
    const __half* gQ = Wq + (size_t)(n0 + lrB) * 512 + lpB * 8;
    const __half* gK = Wk + (size_t)(n0 + lrB) * 512 + lpB * 8;
    const uint32_t dA = sb + (uint32_t)(lrA * SROW2 + lpA * 16) * 2;
    const uint32_t dB = sb + (uint32_t)(lrB * SROW2 + lpB * 8) * 2;

#define LOADQK(c, bsel) { \
        const uint32_t soff = (uint32_t)(bsel) * (STAGEQK * 2); \
        const int ko = (c) * 32; \
        CPASYNC(dA + soff + 0,  gA + ko); \
        CPASYNC(dA + soff + 16, gA + ko + 8); \
        CPASYNC(dB + soff + A_MAT * 2, gQ + ko); \
        CPASYNC(dB + soff + A_MAT * 2 + B_MAT * 2, gK + ko); \
    }

    float aq[2][4][4], ak[2][4][4];
#pragma unroll
    for (int i = 0; i < 2; i++)
#pragma unroll
        for (int j = 0; j < 4; j++)
#pragma unroll
            for (int k = 0; k < 4; k++) { aq[i][j][k] = 0.0f; ak[i][j][k] = 0.0f; }

    LOADQK(0, 0);
    asm volatile("cp.async.commit_group;" ::: "memory");

    const uint32_t a_row_off =
        (uint32_t)((wm * 32 + (lane & 15)) * SROW2) * 2 + (uint32_t)((lane >> 4) * 16);
    const int bn = wn * 32 + (lane & 7) + ((lane >> 4) << 3);
    const uint32_t b_row_off =
        (uint32_t)(bn * SROW2) * 2 + (uint32_t)(((lane >> 3) & 1) * 16);

    for (int c = 0; c < 16; c++) {
        if (c < 15) {
            LOADQK(c + 1, (c + 1) & 1);
            asm volatile("cp.async.commit_group;" ::: "memory");
            asm volatile("cp.async.wait_group 1;" ::: "memory");
        } else {
            asm volatile("cp.async.wait_group 0;" ::: "memory");
        }
        __syncthreads();

        const uint32_t base = sb + (uint32_t)(c & 1) * (STAGEQK * 2);
#pragma unroll
        for (int kk = 0; kk < 2; kk++) {
            const uint32_t aA = base + a_row_off + kk * 32;
            uint32_t a0[4], a1[4];
            LDSM4(a0, aA);
            LDSM4(a1, aA + 16 * SROW2 * 2);

            const uint32_t bQ = base + A_MAT * 2 + b_row_off + kk * 32;
            const uint32_t bK = bQ + B_MAT * 2;
#pragma unroll
            for (int jp = 0; jp < 2; jp++) {
                uint32_t bq[4], bk[4];
                LDSM4(bq, bQ + jp * 16 * SROW2 * 2);
                LDSM4(bk, bK + jp * 16 * SROW2 * 2);
                MMA(aq[0][2 * jp],     a0, bq[0], bq[1]);
                MMA(aq[1][2 * jp],     a1, bq[0], bq[1]);
                MMA(aq[0][2 * jp + 1], a0, bq[2], bq[3]);
                MMA(aq[1][2 * jp + 1], a1, bq[2], bq[3]);
                MMA(ak[0][2 * jp],     a0, bk[0], bk[1]);
                MMA(ak[1][2 * jp],     a1, bk[0], bk[1]);
                MMA(ak[0][2 * jp + 1], a0, bk[2], bk[3]);
                MMA(ak[1][2 * jp + 1], a1, bk[2], bk[3]);
            }
        }
        __syncthreads();
    }

    // Partial dots over this warp's 32 cols; j = mi*2 + rr indexes 4 row groups.
    float pj[4];
#pragma unroll
    for (int j = 0; j < 4; j++) {
        const int mi = j >> 1, o = (j & 1) * 2;
        float p = 0.0f;
#pragma unroll
        for (int ni = 0; ni < 4; ni++)
            p += aq[mi][ni][o] * ak[mi][ni][o]
               + aq[mi][ni][o + 1] * ak[mi][ni][o + 1];
        p += __shfl_xor_sync(0xFFFFFFFF, p, 1);
        p += __shfl_xor_sync(0xFFFFFFFF, p, 2);
        pj[j] = p;
    }

    // Cross-wn reduction via smem (safe: loop ended with __syncthreads)
    float* buf = (float*)sm;   // 4 wm * 4 j * 8 rows = 128 floats
    if (wn == 1 && (lane & 3) == 0) {
#pragma unroll
        for (int j = 0; j < 4; j++)
            buf[(wm * 4 + j) * 8 + (lane >> 2)] = pj[j];
    }
    __syncthreads();
    if (wn == 0 && (lane & 3) == 0) {
        const int h = blockIdx.x;
#pragma unroll
        for (int j = 0; j < 4; j++) {
            float p = pj[j] + buf[(wm * 4 + j) * 8 + (lane >> 2)];
            const int m = m0 + wm * 32 + (lane >> 2) + (j >> 1) * 16 + (j & 1) * 8;
            const int b = m >> 11, q = m & 2047;
            float sd = p * 0.125f;
            int cnt = SEQ - 1 - q;
            float mx = (cnt > 0) ? fmaxf(sd, 0.0f) : sd;
            float ed = expf(sd - mx);
            float eo = (cnt > 0) ? expf(-mx) : 0.0f;
            float Z = ed + (float)cnt * eo;
            g_sa[(b * 8 + h) * SEQ + q] = ed / Z;
            g_sc[(b * 8 + h) * SEQ + q] = eo / Z;
        }
    }
}

// ---------------------------------------------------------------------------
// fp16x3 GEMM, CTA tile 128x64, BK=32, double-buffered, 2 CTAs/SM.
// MODE 0: fp32 store (output projection)
// MODE 1: fp32 store into C + fused 16-row chunk sums (V projection)
// ---------------------------------------------------------------------------
template<int MODE>
__global__ __launch_bounds__(256, 2) void gemm64(
    const __half* __restrict__ Ah, const __half* __restrict__ Al,
    const __half* __restrict__ Bh, const __half* __restrict__ Bl,
    float* __restrict__ C)
{
    extern __shared__ __half sm[];
    const uint32_t sb = smem_u32(sm);
    const int tid = threadIdx.x;
    const int lane = tid & 31, wid = tid >> 5;
    const int wm = wid & 3, wn = wid >> 2;
    const int n0 = blockIdx.x * 64, m0 = blockIdx.y * 128;

    const int lrA = tid >> 1, lpA = tid & 1;
    const int lrB = tid >> 2, lpB = tid & 3;
    const __half* gAh = Ah + (size_t)(m0 + lrA) * 512 + lpA * 16;
    const __half* gAl = Al + (size_t)(m0 + lrA) * 512 + lpA * 16;
    const __half* gBh = Bh + (size_t)(n0 + lrB) * 512 + lpB * 8;
    const __half* gBl = Bl + (size_t)(n0 + lrB) * 512 + lpB * 8;
    const uint32_t dA = sb + (uint32_t)(lrA * SROW2 + lpA * 16) * 2;
    const uint32_t dB = sb + (uint32_t)(lrB * SROW2 + lpB * 8) * 2;

#define LOADCH64(c, bsel) { \
        const uint32_t soff = (uint32_t)(bsel) * (STAGEH * 2); \
        const int ko = (c) * 32; \
        CPASYNC(dA + soff + 0 * A_MAT * 2 + 0,  gAh + ko); \
        CPASYNC(dA + soff + 0 * A_MAT * 2 + 16, gAh + ko + 8); \
        CPASYNC(dA + soff + 1 * A_MAT * 2 + 0,  gAl + ko); \
        CPASYNC(dA + soff + 1 * A_MAT * 2 + 16, gAl + ko + 8); \
        CPASYNC(dB + soff + 2 * A_MAT * 2 + 0,  gBh + ko); \
        CPASYNC(dB + soff + 2 * A_MAT * 2 + B_MAT * 2, gBl + ko); \
    }

    float acc[2][4][4];
#pragma unroll
    for (int i = 0; i < 2; i++)
#pragma unroll
        for (int j = 0; j < 4; j++)
#pragma unroll
            for (int k = 0; k < 4; k++) acc[i][j][k] = 0.0f;

    LOADCH64(0, 0);
    asm volatile("cp.async.commit_group;" ::: "memory");

    const uint32_t a_row_off =
        (uint32_t)((wm * 32 + (lane & 15)) * SROW2) * 2 + (uint32_t)((lane >> 4) * 16);
    const int bn = wn * 32 + (lane & 7) + ((lane >> 4) << 3);
    const uint32_t b_row_off =
        (uint32_t)(bn * SROW2) * 2 + (uint32_t)(((lane >> 3) & 1) * 16);

    for (int c = 0; c < 16; c++) {
        if (c < 15) {
            LOADCH64(c + 1, (c + 1) & 1);
            asm volatile("cp.async.commit_group;" ::: "memory");
            asm volatile("cp.async.wait_group 1;" ::: "memory");
        } else {
            asm volatile("cp.async.wait_group 0;" ::: "memory");
        }
        __syncthreads();

        const uint32_t base = sb + (uint32_t)(c & 1) * (STAGEH * 2);
#pragma unroll
        for (int kk = 0; kk < 2; kk++) {
            const uint32_t aH = base + a_row_off + kk * 32;
            const uint32_t aL = aH + A_MAT * 2;
            uint32_t ah0[4], ah1[4], al0[4], al1[4];
            LDSM4(ah0, aH);
            LDSM4(ah1, aH + 16 * SROW2 * 2);
            LDSM4(al0, aL);
            LDSM4(al1, aL + 16 * SROW2 * 2);

            const uint32_t bH = base + 2 * A_MAT * 2 + b_row_off + kk * 32;
            const uint32_t bL = bH + B_MAT * 2;
#pragma unroll
            for (int jp = 0; jp < 2; jp++) {
                uint32_t bh[4], bl[4];
                LDSM4(bh, bH + jp * 16 * SROW2 * 2);
                LDSM4(bl, bL + jp * 16 * SROW2 * 2);
                MMA(acc[0][2 * jp],     ah0, bh[0], bh[1]);
                MMA(acc[1][2 * jp],     ah1, bh[0], bh[1]);
                MMA(acc[0][2 * jp + 1], ah0, bh[2], bh[3]);
                MMA(acc[1][2 * jp + 1], ah1, bh[2], bh[3]);
                MMA(acc[0][2 * jp],     al0, bh[0], bh[1]);
                MMA(acc[1][2 * jp],     al1, bh[0], bh[1]);
                MMA(acc[0][2 * jp + 1], al0, bh[2], bh[3]);
                MMA(acc[1][2 * jp + 1], al1, bh[2], bh[3]);
                MMA(acc[0][2 * jp],     ah0, bl[0], bl[1]);
                MMA(acc[1][2 * jp],     ah1, bl[0], bl[1]);
                MMA(acc[0][2 * jp + 1], ah0, bl[2], bl[3]);
                MMA(acc[1][2 * jp + 1], ah1, bl[2], bl[3]);
            }
        }
        __syncthreads();
    }

    const int r0 = m0 + wm * 32 + (lane >> 2);
    const int cb = n0 + wn * 32 + (lane & 3) * 2;

#pragma unroll
    for (int mi = 0; mi < 2; mi++) {
        const int r = r0 + mi * 16;
#pragma unroll
        for (int ni = 0; ni < 4; ni++) {
            const int cg = cb + ni * 8;
            *(float2*)&C[(size_t)r * 512 + cg] =
                make_float2(acc[mi][ni][0], acc[mi][ni][1]);
            *(float2*)&C[(size_t)(r + 8) * 512 + cg] =
                make_float2(acc[mi][ni][2], acc[mi][ni][3]);
        }
    }

    if (MODE == 1) {
        // Fused 16-row chunk sums: mi accumulator split = 16-row split
        const int b = m0 >> 11;
        const int c16 = ((m0 & 2047) >> 4) + wm * 2;
        const int h = n0 >> 6;
        float* cs0 = g_cs + ((size_t)(b * 8 + h) * 128 + c16) * 64;
#pragma unroll
        for (int mi = 0; mi < 2; mi++) {
            float* csb = cs0 + mi * 64;
#pragma unroll
            for (int ni = 0; ni < 4; ni++) {
                float s0 = acc[mi][ni][0] + acc[mi][ni][2];
                float s1 = acc[mi][ni][1] + acc[mi][ni][3];
#pragma unroll
                for (int st = 4; st < 32; st <<= 1) {
                    s0 += __shfl_xor_sync(0xFFFFFFFF, s0, st);
                    s1 += __shfl_xor_sync(0xFFFFFFFF, s1, st);
                }
                if (lane < 4) {
                    const int dh = wn * 32 + (lane << 1) + ni * 8;
                    *(float2*)&csb[dh] = make_float2(s0, s1);
                }
            }
        }
    }
}

// ---------------------------------------------------------------------------
// Warp suffix-scan over the 128 chunk sums per (bh,dh) column.
// 1024 warps: one per column. g_suf[c] = sum_{c2>c} g_cs[c2].
// ---------------------------------------------------------------------------
__global__ __launch_bounds__(256) void suffix_scan()
{
    int gw = blockIdx.x * 8 + (threadIdx.x >> 5);  // 0..1023
    int lane = threadIdx.x & 31;
    int bh = gw >> 6, dh = gw & 63;
    const float* cs = g_cs + (size_t)bh * 128 * 64 + dh;
    float v0 = cs[(lane * 4 + 0) * 64];
    float v1 = cs[(lane * 4 + 1) * 64];
    float v2 = cs[(lane * 4 + 2) * 64];
    float v3 = cs[(lane * 4 + 3) * 64];
    float lsum = v0 + v1 + v2 + v3;
    float x = lsum;
#pragma unroll
    for (int d = 1; d < 32; d <<= 1) {
        float y = __shfl_down_sync(0xFFFFFFFF, x, d);
        if (lane + d < 32) x += y;
    }
    float run = x - lsum;   // sum over chunks in lanes > lane
    float* suf = g_suf + (size_t)bh * 128 * 64 + dh;
    suf[(lane * 4 + 3) * 64] = run;
    suf[(lane * 4 + 2) * 64] = run + v3;
    suf[(lane * 4 + 1) * 64] = run + v3 + v2;
    suf[(lane * 4 + 0) * 64] = run + v3 + v2 + v1;
}

// ---------------------------------------------------------------------------
// Scan: z[q] = a_q*v[q] + c_q*suffix_{p>q} v[p]. 16-row chunks, suffix lookup.
// ---------------------------------------------------------------------------
__global__ __launch_bounds__(256) void v_scan()
{
    int bh = blockIdx.y;
    int chunk = blockIdx.x * 4 + (threadIdx.x >> 6);   // 0..127
    int dh = threadIdx.x & 63;
    int b = bh >> 3, h = bh & 7;

    float run = g_suf[((size_t)bh * 128 + chunk) * 64 + dh];

    const float* sa = g_sa + bh * SEQ;
    const float* sc = g_sc + bh * SEQ;
    const int q0 = chunk * 16;
#pragma unroll
    for (int i = 15; i >= 0; i--) {
        int q = q0 + i;
        size_t row = (size_t)(b * SEQ + q) * DMODEL + h * DH + dh;
        float v = g_V[row];
        float z = sa[q] * v + sc[q] * run;
        __half zh = __float2half_rn(z);
        g_zh[row] = zh;
        g_zl[row] = __float2half_rn(z - __half2float(zh));
        run += v;
    }
}

// ---------------------------------------------------------------------------
extern "C" void kernel_launch(void* const* d_in, const int* in_sizes, int n_in,
                              void* d_out, int out_size)
{
    const float* x  = (const float*)d_in[0];
    const float* WQ = (const float*)d_in[1];
    const float* WK = (const float*)d_in[2];
    const float* WV = (const float*)d_in[3];
    const float* WO = (const float*)d_in[4];
    float* out = (float*)d_out;

    cudaFuncSetAttribute(qk64, cudaFuncAttributeMaxDynamicSharedMemorySize,
                         SMEMQK64);
    cudaFuncSetAttribute(gemm64<0>, cudaFuncAttributeMaxDynamicSharedMemorySize,
                         SMEM64);
    cudaFuncSetAttribute(gemm64<1>, cudaFuncAttributeMaxDynamicSharedMemorySize,
                         SMEM64);

    __half *xh, *xl, *wh, *wl, *oh, *ol, *zh, *zl;
    float *gv;
    cudaGetSymbolAddress((void**)&xh, g_xh);
    cudaGetSymbolAddress((void**)&xl, g_xl);
    cudaGetSymbolAddress((void**)&wh, g_wh);
    cudaGetSymbolAddress((void**)&wl, g_wl);
    cudaGetSymbolAddress((void**)&oh, g_oh);
    cudaGetSymbolAddress((void**)&ol, g_ol);
    cudaGetSymbolAddress((void**)&zh, g_zh);
    cudaGetSymbolAddress((void**)&zl, g_zl);
    cudaGetSymbolAddress((void**)&gv, g_V);

    convert_all<<<3072, 256>>>(x, WQ, WK, WV, WO);

    // QK-diag (one head per CTA column): writes g_sa/g_sc directly
    qk64<<<dim3(8, 32), 256, SMEMQK64>>>(xh, wh, wh + 512 * 512);

    // V projection (fp16x3), fp32 V store + fused 16-row chunk sums
    gemm64<1><<<dim3(8, 32), 256, SMEM64>>>(
        xh, xl, wh + 1024 * 512, wl + 1024 * 512, gv);

    suffix_scan<<<128, 256>>>();
    v_scan<<<dim3(32, 16), 256>>>();

    // Output projection (fp16x3)
    gemm64<0><<<dim3(8, 32), 256, SMEM64>>>(zh, zl, oh, ol, out);
}

// round 12
// speedup vs baseline: 1.1897x; 1.0143x over previous
#include <cuda_runtime.h>
#include <cuda_fp16.h>
#include <math.h>
#include <stdint.h>

#define SEQ     2048
#define DMODEL  512
#define NH      8
#define DH      64
#define BATCH   2
#define MTOT    4096

// ---------------- scratch (__device__ globals, allocation-free) -------------
__device__ __half g_xh[MTOT * DMODEL];
__device__ __half g_xl[MTOT * DMODEL];
__device__ __half g_wh[3 * DMODEL * DMODEL];   // [Wq;Wk;Wv] rows 0..1535 (hi)
__device__ __half g_wl[3 * DMODEL * DMODEL];   // lo used only for Wv range
__device__ __half g_oh[DMODEL * DMODEL];
__device__ __half g_ol[DMODEL * DMODEL];
__device__ float  g_V [MTOT * DMODEL];
__device__ __half g_zh[MTOT * DMODEL];
__device__ __half g_zl[MTOT * DMODEL];
__device__ float  g_sa[16 * SEQ];
__device__ float  g_sc[16 * SEQ];
__device__ float  g_cs [16 * 64 * 128];  // [bh][dh][chunk16] V column sums (transposed!)
__device__ float  g_suf[16 * 128 * 64];  // [bh][chunk16][dh] suffix sums

// ---------------------------------------------------------------------------
__device__ __forceinline__ uint32_t smem_u32(const void* p) {
    uint32_t a;
    asm("{ .reg .u64 t; cvta.to.shared.u64 t, %1; cvt.u32.u64 %0, t; }"
        : "=r"(a) : "l"(p));
    return a;
}

#define CPASYNC(d, s) \
    asm volatile("cp.async.cg.shared.global [%0], [%1], 16;" \
                 :: "r"(d), "l"(s) : "memory")

#define LDSM4(r, a) \
    asm volatile("ldmatrix.sync.aligned.m8n8.x4.shared.b16 {%0,%1,%2,%3}, [%4];" \
                 : "=r"((r)[0]), "=r"((r)[1]), "=r"((r)[2]), "=r"((r)[3]) \
                 : "r"(a))

#define MMA(d, a, b0, b1) \
    asm volatile("mma.sync.aligned.m16n8k16.row.col.f32.f16.f16.f32 " \
                 "{%0,%1,%2,%3},{%4,%5,%6,%7},{%8,%9},{%0,%1,%2,%3};" \
                 : "+f"((d)[0]), "+f"((d)[1]), "+f"((d)[2]), "+f"((d)[3]) \
                 : "r"((a)[0]), "r"((a)[1]), "r"((a)[2]), "r"((a)[3]), \
                   "r"(b0), "r"(b1))

// 128x64 BK=32 tiling
#define SROW2 40                         // 32 halves + 8 pad
#define A_MAT (128 * SROW2)              // halves
#define B_MAT (64 * SROW2)
#define STAGEH (2 * A_MAT + 2 * B_MAT)   // gemm64 stage (Ah,Al,Bh,Bl)
#define SMEM64 (2 * STAGEH * 2)          // 61440 B
#define STAGEQK (A_MAT + 2 * B_MAT)      // qk64 stage (A,BQ,BK)
#define SMEMQK64 (2 * STAGEQK * 2)       // 40960 B

// ---------------------------------------------------------------------------
// fp32 -> fp16 hi/lo conversion (lo skipped for Wq/Wk)
// ---------------------------------------------------------------------------
__global__ __launch_bounds__(256) void convert_all(
    const float* __restrict__ x,  const float* __restrict__ wq,
    const float* __restrict__ wk, const float* __restrict__ wv,
    const float* __restrict__ wo)
{
    int t = blockIdx.x * 256 + threadIdx.x;       // float4 index, 786432 total
    const float* src;
    __half *dh, *dl;
    int idx;
    bool wantLo = true;
    if (t < 524288)      { src = x;  dh = g_xh;          dl = g_xl;          idx = t; }
    else if (t < 589824) { src = wq; dh = g_wh;          dl = g_wl;          idx = t - 524288; wantLo = false; }
    else if (t < 655360) { src = wk; dh = g_wh + 262144; dl = g_wl + 262144; idx = t - 589824; wantLo = false; }
    else if (t < 720896) { src = wv; dh = g_wh + 524288; dl = g_wl + 524288; idx = t - 655360; }
    else                 { src = wo; dh = g_oh;          dl = g_ol;          idx = t - 720896; }

    float4 v = ((const float4*)src)[idx];
    __half h0 = __float2half_rn(v.x), h1 = __float2half_rn(v.y);
    __half h2 = __float2half_rn(v.z), h3 = __float2half_rn(v.w);
    __half2* ph = (__half2*)(dh + idx * 4);
    ph[0] = __halves2half2(h0, h1); ph[1] = __halves2half2(h2, h3);
    if (wantLo) {
        __half l0 = __float2half_rn(v.x - __half2float(h0));
        __half l1 = __float2half_rn(v.y - __half2float(h1));
        __half l2 = __float2half_rn(v.z - __half2float(h2));
        __half l3 = __float2half_rn(v.w - __half2float(h3));
        __half2* pl = (__half2*)(dl + idx * 4);
        pl[0] = __halves2half2(l0, l1); pl[1] = __halves2half2(l2, l3);
    }
}

// ---------------------------------------------------------------------------
// QK-diag, 128x64 tile, BK=32, 2 CTA/SM. One head per CTA (bx = head).
// ---------------------------------------------------------------------------
__global__ __launch_bounds__(256, 2) void qk64(
    const __half* __restrict__ xh,
    const __half* __restrict__ Wq,
    const __half* __restrict__ Wk)
{
    extern __shared__ __half sm[];
    const uint32_t sb = smem_u32(sm);
    const int tid = threadIdx.x;
    const int lane = tid & 31, wid = tid >> 5;
    const int wm = wid & 3, wn = wid >> 2;
    const int n0 = blockIdx.x * 64, m0 = blockIdx.y * 128;

    const int lrA = tid >> 1, lpA = tid & 1;
    const int lrB = tid >> 2, lpB = tid & 3;
    const __half* gA = xh + (size_t)(m0 + lrA) * 512 + lpA * 16;
    const __half* gQ = Wq + (size_t)(n0 + lrB) * 512 + lpB * 8;
    const __half* gK = Wk + (size_t)(n0 + lrB) * 512 + lpB * 8;
    const uint32_t dA = sb + (uint32_t)(lrA * SROW2 + lpA * 16) * 2;
    const uint32_t dB = sb + (uint32_t)(lrB * SROW2 + lpB * 8) * 2;

#define LOADQK(c, bsel) { \
        const uint32_t soff = (uint32_t)(bsel) * (STAGEQK * 2); \
        const int ko = (c) * 32; \
        CPASYNC(dA + soff + 0,  gA + ko); \
        CPASYNC(dA + soff + 16, gA + ko + 8); \
        CPASYNC(dB + soff + A_MAT * 2, gQ + ko); \
        CPASYNC(dB + soff + A_MAT * 2 + B_MAT * 2, gK + ko); \
    }

    float aq[2][4][4], ak[2][4][4];
#pragma unroll
    for (int i = 0; i < 2; i++)
#pragma unroll
        for (int j = 0; j < 4; j++)
#pragma unroll
            for (int k = 0; k < 4; k++) { aq[i][j][k] = 0.0f; ak[i][j][k] = 0.0f; }

    LOADQK(0, 0);
    asm volatile("cp.async.commit_group;" ::: "memory");

    const uint32_t a_row_off =
        (uint32_t)((wm * 32 + (lane & 15)) * SROW2) * 2 + (uint32_t)((lane >> 4) * 16);
    const int bn = wn * 32 + (lane & 7) + ((lane >> 4) << 3);
    const uint32_t b_row_off =
        (uint32_t)(bn * SROW2) * 2 + (uint32_t)(((lane >> 3) & 1) * 16);

    for (int c = 0; c < 16; c++) {
        if (c < 15) {
            LOADQK(c + 1, (c + 1) & 1);
            asm volatile("cp.async.commit_group;" ::: "memory");
            asm volatile("cp.async.wait_group 1;" ::: "memory");
        } else {
            asm volatile("cp.async.wait_group 0;" ::: "memory");
        }
        __syncthreads();

        const uint32_t base = sb + (uint32_t)(c & 1) * (STAGEQK * 2);
#pragma unroll
        for (int kk = 0; kk < 2; kk++) {
            const uint32_t aA = base + a_row_off + kk * 32;
            uint32_t a0[4], a1[4];
            LDSM4(a0, aA);
            LDSM4(a1, aA + 16 * SROW2 * 2);

            const uint32_t bQ = base + A_MAT * 2 + b_row_off + kk * 32;
            const uint32_t bK = bQ + B_MAT * 2;
#pragma unroll
            for (int jp = 0; jp < 2; jp++) {
                uint32_t bq[4], bk[4];
                LDSM4(bq, bQ + jp * 16 * SROW2 * 2);
                LDSM4(bk, bK + jp * 16 * SROW2 * 2);
                MMA(aq[0][2 * jp],     a0, bq[0], bq[1]);
                MMA(aq[1][2 * jp],     a1, bq[0], bq[1]);
                MMA(aq[0][2 * jp + 1], a0, bq[2], bq[3]);
                MMA(aq[1][2 * jp + 1], a1, bq[2], bq[3]);
                MMA(ak[0][2 * jp],     a0, bk[0], bk[1]);
                MMA(ak[1][2 * jp],     a1, bk[0], bk[1]);
                MMA(ak[0][2 * jp + 1], a0, bk[2], bk[3]);
                MMA(ak[1][2 * jp + 1], a1, bk[2], bk[3]);
            }
        }
        __syncthreads();
    }

    float pj[4];
#pragma unroll
    for (int j = 0; j < 4; j++) {
        const int mi = j >> 1, o = (j & 1) * 2;
        float p = 0.0f;
#pragma unroll
        for (int ni = 0; ni < 4; ni++)
            p += aq[mi][ni][o] * ak[mi][ni][o]
               + aq[mi][ni][o + 1] * ak[mi][ni][o + 1];
        p += __shfl_xor_sync(0xFFFFFFFF, p, 1);
        p += __shfl_xor_sync(0xFFFFFFFF, p, 2);
        pj[j] = p;
    }

    float* buf = (float*)sm;   // 128 floats
    if (wn == 1 && (lane & 3) == 0) {
#pragma unroll
        for (int j = 0; j < 4; j++)
            buf[(wm * 4 + j) * 8 + (lane >> 2)] = pj[j];
    }
    __syncthreads();
    if (wn == 0 && (lane & 3) == 0) {
        const int h = blockIdx.x;
#pragma unroll
        for (int j = 0; j < 4; j++) {
            float p = pj[j] + buf[(wm * 4 + j) * 8 + (lane >> 2)];
            const int m = m0 + wm * 32 + (lane >> 2) + (j >> 1) * 16 + (j & 1) * 8;
            const int b = m >> 11, q = m & 2047;
            float sd = p * 0.125f;
            int cnt = SEQ - 1 - q;
            float mx = (cnt > 0) ? fmaxf(sd, 0.0f) : sd;
            float ed = expf(sd - mx);
            float eo = (cnt > 0) ? expf(-mx) : 0.0f;
            float Z = ed + (float)cnt * eo;
            g_sa[(b * 8 + h) * SEQ + q] = ed / Z;
            g_sc[(b * 8 + h) * SEQ + q] = eo / Z;
        }
    }
}

// ---------------------------------------------------------------------------
// fp16x3 GEMM, CTA tile 128x64, BK=32, double-buffered, 2 CTAs/SM.
// MODE 0: fp32 store (output projection)
// MODE 1: fp32 store into C + fused 16-row chunk sums (V projection, transposed cs)
// ---------------------------------------------------------------------------
template<int MODE>
__global__ __launch_bounds__(256, 2) void gemm64(
    const __half* __restrict__ Ah, const __half* __restrict__ Al,
    const __half* __restrict__ Bh, const __half* __restrict__ Bl,
    float* __restrict__ C)
{
    extern __shared__ __half sm[];
    const uint32_t sb = smem_u32(sm);
    const int tid = threadIdx.x;
    const int lane = tid & 31, wid = tid >> 5;
    const int wm = wid & 3, wn = wid >> 2;
    const int n0 = blockIdx.x * 64, m0 = blockIdx.y * 128;

    const int lrA = tid >> 1, lpA = tid & 1;
    const int lrB = tid >> 2, lpB = tid & 3;
    const __half* gAh = Ah + (size_t)(m0 + lrA) * 512 + lpA * 16;
    const __half* gAl = Al + (size_t)(m0 + lrA) * 512 + lpA * 16;
    const __half* gBh = Bh + (size_t)(n0 + lrB) * 512 + lpB * 8;
    const __half* gBl = Bl + (size_t)(n0 + lrB) * 512 + lpB * 8;
    const uint32_t dA = sb + (uint32_t)(lrA * SROW2 + lpA * 16) * 2;
    const uint32_t dB = sb + (uint32_t)(lrB * SROW2 + lpB * 8) * 2;

#define LOADCH64(c, bsel) { \
        const uint32_t soff = (uint32_t)(bsel) * (STAGEH * 2); \
        const int ko = (c) * 32; \
        CPASYNC(dA + soff + 0 * A_MAT * 2 + 0,  gAh + ko); \
        CPASYNC(dA + soff + 0 * A_MAT * 2 + 16, gAh + ko + 8); \
        CPASYNC(dA + soff + 1 * A_MAT * 2 + 0,  gAl + ko); \
        CPASYNC(dA + soff + 1 * A_MAT * 2 + 16, gAl + ko + 8); \
        CPASYNC(dB + soff + 2 * A_MAT * 2 + 0,  gBh + ko); \
        CPASYNC(dB + soff + 2 * A_MAT * 2 + B_MAT * 2, gBl + ko); \
    }

    float acc[2][4][4];
#pragma unroll
    for (int i = 0; i < 2; i++)
#pragma unroll
        for (int j = 0; j < 4; j++)
#pragma unroll
            for (int k = 0; k < 4; k++) acc[i][j][k] = 0.0f;

    LOADCH64(0, 0);
    asm volatile("cp.async.commit_group;" ::: "memory");

    const uint32_t a_row_off =
        (uint32_t)((wm * 32 + (lane & 15)) * SROW2) * 2 + (uint32_t)((lane >> 4) * 16);
    const int bn = wn * 32 + (lane & 7) + ((lane >> 4) << 3);
    const uint32_t b_row_off =
        (uint32_t)(bn * SROW2) * 2 + (uint32_t)(((lane >> 3) & 1) * 16);

    for (int c = 0; c < 16; c++) {
        if (c < 15) {
            LOADCH64(c + 1, (c + 1) & 1);
            asm volatile("cp.async.commit_group;" ::: "memory");
            asm volatile("cp.async.wait_group 1;" ::: "memory");
        } else {
            asm volatile("cp.async.wait_group 0;" ::: "memory");
        }
        __syncthreads();

        const uint32_t base = sb + (uint32_t)(c & 1) * (STAGEH * 2);
#pragma unroll
        for (int kk = 0; kk < 2; kk++) {
            const uint32_t aH = base + a_row_off + kk * 32;
            const uint32_t aL = aH + A_MAT * 2;
            uint32_t ah0[4], ah1[4], al0[4], al1[4];
            LDSM4(ah0, aH);
            LDSM4(ah1, aH + 16 * SROW2 * 2);
            LDSM4(al0, aL);
            LDSM4(al1, aL + 16 * SROW2 * 2);

            const uint32_t bH = base + 2 * A_MAT * 2 + b_row_off + kk * 32;
            const uint32_t bL = bH + B_MAT * 2;
#pragma unroll
            for (int jp = 0; jp < 2; jp++) {
                uint32_t bh[4], bl[4];
                LDSM4(bh, bH + jp * 16 * SROW2 * 2);
                LDSM4(bl, bL + jp * 16 * SROW2 * 2);
                MMA(acc[0][2 * jp],     ah0, bh[0], bh[1]);
                MMA(acc[1][2 * jp],     ah1, bh[0], bh[1]);
                MMA(acc[0][2 * jp + 1], ah0, bh[2], bh[3]);
                MMA(acc[1][2 * jp + 1], ah1, bh[2], bh[3]);
                MMA(acc[0][2 * jp],     al0, bh[0], bh[1]);
                MMA(acc[1][2 * jp],     al1, bh[0], bh[1]);
                MMA(acc[0][2 * jp + 1], al0, bh[2], bh[3]);
                MMA(acc[1][2 * jp + 1], al1, bh[2], bh[3]);
                MMA(acc[0][2 * jp],     ah0, bl[0], bl[1]);
                MMA(acc[1][2 * jp],     ah1, bl[0], bl[1]);
                MMA(acc[0][2 * jp + 1], ah0, bl[2], bl[3]);
                MMA(acc[1][2 * jp + 1], ah1, bl[2], bl[3]);
            }
        }
        __syncthreads();
    }

    const int r0 = m0 + wm * 32 + (lane >> 2);
    const int cb = n0 + wn * 32 + (lane & 3) * 2;

#pragma unroll
    for (int mi = 0; mi < 2; mi++) {
        const int r = r0 + mi * 16;
#pragma unroll
        for (int ni = 0; ni < 4; ni++) {
            const int cg = cb + ni * 8;
            *(float2*)&C[(size_t)r * 512 + cg] =
                make_float2(acc[mi][ni][0], acc[mi][ni][1]);
            *(float2*)&C[(size_t)(r + 8) * 512 + cg] =
                make_float2(acc[mi][ni][2], acc[mi][ni][3]);
        }
    }

    if (MODE == 1) {
        // Fused 16-row chunk sums, stored TRANSPOSED: g_cs[bh][dh][chunk]
        const int b = m0 >> 11;
        const int c16 = ((m0 & 2047) >> 4) + wm * 2;
        const int h = n0 >> 6;
        const int bh = b * 8 + h;
#pragma unroll
        for (int mi = 0; mi < 2; mi++) {
            const int chunk = c16 + mi;
#pragma unroll
            for (int ni = 0; ni < 4; ni++) {
                float s0 = acc[mi][ni][0] + acc[mi][ni][2];
                float s1 = acc[mi][ni][1] + acc[mi][ni][3];
#pragma unroll
                for (int st = 4; st < 32; st <<= 1) {
                    s0 += __shfl_xor_sync(0xFFFFFFFF, s0, st);
                    s1 += __shfl_xor_sync(0xFFFFFFFF, s1, st);
                }
                if (lane < 4) {
                    const int dh = wn * 32 + (lane << 1) + ni * 8;
                    g_cs[((size_t)bh * 64 + dh)     * 128 + chunk] = s0;
                    g_cs[((size_t)bh * 64 + dh + 1) * 128 + chunk] = s1;
                }
            }
        }
    }
}

// ---------------------------------------------------------------------------
// Warp suffix-scan over 128 chunk sums per (bh,dh) column.
// g_cs is [bh][dh][chunk] -> each warp reads ONE coalesced float4 per lane.
// Output g_suf is [bh][chunk][dh] (scattered writes, fire-and-forget).
// ---------------------------------------------------------------------------
__global__ __launch_bounds__(256) void suffix_scan()
{
    int gw = blockIdx.x * 8 + (threadIdx.x >> 5);  // 0..1023
    int lane = threadIdx.x & 31;
    int bh = gw >> 6, dh = gw & 63;
    const float4* cs = (const float4*)(g_cs + ((size_t)bh * 64 + dh) * 128);
    float4 v = cs[lane];
    float lsum = v.x + v.y + v.z + v.w;
    float x = lsum;
#pragma unroll
    for (int d = 1; d < 32; d <<= 1) {
        float y = __shfl_down_sync(0xFFFFFFFF, x, d);
        if (lane + d < 32) x += y;
    }
    float run = x - lsum;   // sum over chunks in lanes > lane
    float* suf = g_suf + (size_t)bh * 128 * 64 + dh;
    suf[(lane * 4 + 3) * 64] = run;
    suf[(lane * 4 + 2) * 64] = run + v.w;
    suf[(lane * 4 + 1) * 64] = run + v.w + v.z;
    suf[(lane * 4 + 0) * 64] = run + v.w + v.z + v.y;
}

// ---------------------------------------------------------------------------
// Scan: z[q] = a_q*v[q] + c_q*suffix_{p>q} v[p]. 16-row chunks, batched loads.
// ---------------------------------------------------------------------------
__global__ __launch_bounds__(256) void v_scan()
{
    int bh = blockIdx.y;
    int chunk = blockIdx.x * 4 + (threadIdx.x >> 6);   // 0..127
    int dh = threadIdx.x & 63;
    int b = bh >> 3, h = bh & 7;
    const int q0 = chunk * 16;

    // Batch all loads up front (MLP=16+)
    const float* vbase = g_V + (size_t)(b * SEQ + q0) * DMODEL + h * DH + dh;
    float v[16];
#pragma unroll
    for (int i = 0; i < 16; i++) v[i] = vbase[i * DMODEL];

    float wa[16], wc[16];
    const float* sa = g_sa + bh * SEQ + q0;
    const float* sc = g_sc + bh * SEQ + q0;
#pragma unroll
    for (int i = 0; i < 16; i++) { wa[i] = sa[i]; wc[i] = sc[i]; }

    float run = g_suf[((size_t)bh * 128 + chunk) * 64 + dh];

    __half* zhb = g_zh + (size_t)(b * SEQ + q0) * DMODEL + h * DH + dh;
    __half* zlb = g_zl + (size_t)(b * SEQ + q0) * DMODEL + h * DH + dh;
#pragma unroll
    for (int i = 15; i >= 0; i--) {
        float z = wa[i] * v[i] + wc[i] * run;
        __half zh = __float2half_rn(z);
        zhb[i * DMODEL] = zh;
        zlb[i * DMODEL] = __float2half_rn(z - __half2float(zh));
        run += v[i];
    }
}

// ---------------------------------------------------------------------------
extern "C" void kernel_launch(void* const* d_in, const int* in_sizes, int n_in,
                              void* d_out, int out_size)
{
    const float* x  = (const float*)d_in[0];
    const float* WQ = (const float*)d_in[1];
    const float* WK = (const float*)d_in[2];
    const float* WV = (const float*)d_in[3];
    const float* WO = (const float*)d_in[4];
    float* out = (float*)d_out;

    cudaFuncSetAttribute(qk64, cudaFuncAttributeMaxDynamicSharedMemorySize,
                         SMEMQK64);
    cudaFuncSetAttribute(gemm64<0>, cudaFuncAttributeMaxDynamicSharedMemorySize,
                         SMEM64);
    cudaFuncSetAttribute(gemm64<1>, cudaFuncAttributeMaxDynamicSharedMemorySize,
                         SMEM64);

    __half *xh, *xl, *wh, *wl, *oh, *ol, *zh, *zl;
    float *gv;
    cudaGetSymbolAddress((void**)&xh, g_xh);
    cudaGetSymbolAddress((void**)&xl, g_xl);
    cudaGetSymbolAddress((void**)&wh, g_wh);
    cudaGetSymbolAddress((void**)&wl, g_wl);
    cudaGetSymbolAddress((void**)&oh, g_oh);
    cudaGetSymbolAddress((void**)&ol, g_ol);
    cudaGetSymbolAddress((void**)&zh, g_zh);
    cudaGetSymbolAddress((void**)&zl, g_zl);
    cudaGetSymbolAddress((void**)&gv, g_V);

    convert_all<<<3072, 256>>>(x, WQ, WK, WV, WO);

    // QK-diag (one head per CTA column): writes g_sa/g_sc directly
    qk64<<<dim3(8, 32), 256, SMEMQK64>>>(xh, wh, wh + 512 * 512);

    // V projection (fp16x3), fp32 V store + fused transposed chunk sums
    gemm64<1><<<dim3(8, 32), 256, SMEM64>>>(
        xh, xl, wh + 1024 * 512, wl + 1024 * 512, gv);

    suffix_scan<<<128, 256>>>();
    v_scan<<<dim3(32, 16), 256>>>();

    // Output projection (fp16x3)
    gemm64<0><<<dim3(8, 32), 256, SMEM64>>>(zh, zl, oh, ol, out);
}

// round 13
// speedup vs baseline: 1.2070x; 1.0145x over previous
#include <cuda_runtime.h>
#include <cuda_fp16.h>
#include <math.h>
#include <stdint.h>

#define SEQ     2048
#define DMODEL  512
#define NH      8
#define DH      64
#define BATCH   2
#define MTOT    4096

// ---------------- scratch (__device__ globals, allocation-free) -------------
__device__ __half g_xh[MTOT * DMODEL];
__device__ __half g_xl[MTOT * DMODEL];
__device__ __half g_wh[3 * DMODEL * DMODEL];   // [Wq;Wk;Wv] rows 0..1535 (hi)
__device__ __half g_wl[3 * DMODEL * DMODEL];   // lo used only for Wv range
__device__ __half g_oh[DMODEL * DMODEL];
__device__ __half g_ol[DMODEL * DMODEL];
__device__ float  g_V [MTOT * DMODEL];
__device__ __half g_zh[MTOT * DMODEL];
__device__ __half g_zl[MTOT * DMODEL];
__device__ float  g_sa[16 * SEQ];
__device__ float  g_sc[16 * SEQ];
__device__ float  g_cs[16 * 128 * 64];   // [bh][chunk16][dh] fine V sums
__device__ float  g_cb[16 * 16 * 64];    // [bh][mblk128][dh] coarse V sums

// ---------------------------------------------------------------------------
__device__ __forceinline__ uint32_t smem_u32(const void* p) {
    uint32_t a;
    asm("{ .reg .u64 t; cvta.to.shared.u64 t, %1; cvt.u32.u64 %0, t; }"
        : "=r"(a) : "l"(p));
    return a;
}

#define CPASYNC(d, s) \
    asm volatile("cp.async.cg.shared.global [%0], [%1], 16;" \
                 :: "r"(d), "l"(s) : "memory")

#define LDSM4(r, a) \
    asm volatile("ldmatrix.sync.aligned.m8n8.x4.shared.b16 {%0,%1,%2,%3}, [%4];" \
                 : "=r"((r)[0]), "=r"((r)[1]), "=r"((r)[2]), "=r"((r)[3]) \
                 : "r"(a))

#define MMA(d, a, b0, b1) \
    asm volatile("mma.sync.aligned.m16n8k16.row.col.f32.f16.f16.f32 " \
                 "{%0,%1,%2,%3},{%4,%5,%6,%7},{%8,%9},{%0,%1,%2,%3};" \
                 : "+f"((d)[0]), "+f"((d)[1]), "+f"((d)[2]), "+f"((d)[3]) \
                 : "r"((a)[0]), "r"((a)[1]), "r"((a)[2]), "r"((a)[3]), \
                   "r"(b0), "r"(b1))

// 128x64 BK=32 tiling
#define SROW2 40                         // 32 halves + 8 pad
#define A_MAT (128 * SROW2)              // halves
#define B_MAT (64 * SROW2)
#define STAGEH (2 * A_MAT + 2 * B_MAT)   // V stage (Ah,Al,Bh,Bl)
#define SMEM64 (2 * STAGEH * 2)          // 61440 B
#define STAGEQK (A_MAT + 2 * B_MAT)      // QK stage (A,BQ,BK)

// ---------------------------------------------------------------------------
// fp32 -> fp16 hi/lo conversion (lo skipped for Wq/Wk)
// ---------------------------------------------------------------------------
__global__ __launch_bounds__(256) void convert_all(
    const float* __restrict__ x,  const float* __restrict__ wq,
    const float* __restrict__ wk, const float* __restrict__ wv,
    const float* __restrict__ wo)
{
    int t = blockIdx.x * 256 + threadIdx.x;       // float4 index, 786432 total
    const float* src;
    __half *dh, *dl;
    int idx;
    bool wantLo = true;
    if (t < 524288)      { src = x;  dh = g_xh;          dl = g_xl;          idx = t; }
    else if (t < 589824) { src = wq; dh = g_wh;          dl = g_wl;          idx = t - 524288; wantLo = false; }
    else if (t < 655360) { src = wk; dh = g_wh + 262144; dl = g_wl + 262144; idx = t - 589824; wantLo = false; }
    else if (t < 720896) { src = wv; dh = g_wh + 524288; dl = g_wl + 524288; idx = t - 655360; }
    else                 { src = wo; dh = g_oh;          dl = g_ol;          idx = t - 720896; }

    float4 v = ((const float4*)src)[idx];
    __half h0 = __float2half_rn(v.x), h1 = __float2half_rn(v.y);
    __half h2 = __float2half_rn(v.z), h3 = __float2half_rn(v.w);
    __half2* ph = (__half2*)(dh + idx * 4);
    ph[0] = __halves2half2(h0, h1); ph[1] = __halves2half2(h2, h3);
    if (wantLo) {
        __half l0 = __float2half_rn(v.x - __half2float(h0));
        __half l1 = __float2half_rn(v.y - __half2float(h1));
        __half l2 = __float2half_rn(v.z - __half2float(h2));
        __half l3 = __float2half_rn(v.w - __half2float(h3));
        __half2* pl = (__half2*)(dl + idx * 4);
        pl[0] = __halves2half2(l0, l1); pl[1] = __halves2half2(l2, l3);
    }
}

// ---------------------------------------------------------------------------
// Fused QK-diag + V-projection. grid (16, 32), both branches 128x64/BK=32,
// 2 CTAs/SM. bx<8: QK-diag for head bx. bx>=8: V GEMM cols (bx-8)*64,
// epilogue stores fp32 V + fine 16-row chunk sums + coarse 128-row sums.
// ---------------------------------------------------------------------------
__global__ __launch_bounds__(256, 2) void qkv_fused(
    const __half* __restrict__ xh, const __half* __restrict__ xl,
    const __half* __restrict__ wh, const __half* __restrict__ wl,
    float* __restrict__ V)
{
    extern __shared__ __half sm[];
    const uint32_t sb = smem_u32(sm);
    const int tid = threadIdx.x;
    const int lane = tid & 31, wid = tid >> 5;
    const int wm = wid & 3, wn = wid >> 2;
    const int m0 = blockIdx.y * 128;

    const int lrA = tid >> 1, lpA = tid & 1;
    const int lrB = tid >> 2, lpB = tid & 3;
    const uint32_t dA = sb + (uint32_t)(lrA * SROW2 + lpA * 16) * 2;
    const uint32_t dB = sb + (uint32_t)(lrB * SROW2 + lpB * 8) * 2;

    const uint32_t a_row_off =
        (uint32_t)((wm * 32 + (lane & 15)) * SROW2) * 2 + (uint32_t)((lane >> 4) * 16);
    const int bn = wn * 32 + (lane & 7) + ((lane >> 4) << 3);
    const uint32_t b_row_off =
        (uint32_t)(bn * SROW2) * 2 + (uint32_t)(((lane >> 3) & 1) * 16);

    if (blockIdx.x < 8) {
        // ================= QK-diagonal branch (plain fp16) ==================
        const int n0 = blockIdx.x * 64;   // head = blockIdx.x
        const __half* gA = xh + (size_t)(m0 + lrA) * 512 + lpA * 16;
        const __half* gQ = wh + (size_t)(n0 + lrB) * 512 + lpB * 8;
        const __half* gK = wh + 512 * 512 + (size_t)(n0 + lrB) * 512 + lpB * 8;

#define LOADQK(c, bsel) { \
        const uint32_t soff = (uint32_t)(bsel) * (STAGEQK * 2); \
        const int ko = (c) * 32; \
        CPASYNC(dA + soff + 0,  gA + ko); \
        CPASYNC(dA + soff + 16, gA + ko + 8); \
        CPASYNC(dB + soff + A_MAT * 2, gQ + ko); \
        CPASYNC(dB + soff + A_MAT * 2 + B_MAT * 2, gK + ko); \
    }

        float aq[2][4][4], ak[2][4][4];
#pragma unroll
        for (int i = 0; i < 2; i++)
#pragma unroll
            for (int j = 0; j < 4; j++)
#pragma unroll
                for (int k = 0; k < 4; k++) { aq[i][j][k] = 0.0f; ak[i][j][k] = 0.0f; }

        LOADQK(0, 0);
        asm volatile("cp.async.commit_group;" ::: "memory");

        for (int c = 0; c < 16; c++) {
            if (c < 15) {
                LOADQK(c + 1, (c + 1) & 1);
                asm volatile("cp.async.commit_group;" ::: "memory");
                asm volatile("cp.async.wait_group 1;" ::: "memory");
            } else {
                asm volatile("cp.async.wait_group 0;" ::: "memory");
            }
            __syncthreads();

            const uint32_t base = sb + (uint32_t)(c & 1) * (STAGEQK * 2);
#pragma unroll
            for (int kk = 0; kk < 2; kk++) {
                const uint32_t aA = base + a_row_off + kk * 32;
                uint32_t a0[4], a1[4];
                LDSM4(a0, aA);
                LDSM4(a1, aA + 16 * SROW2 * 2);

                const uint32_t bQ = base + A_MAT * 2 + b_row_off + kk * 32;
                const uint32_t bK = bQ + B_MAT * 2;
#pragma unroll
                for (int jp = 0; jp < 2; jp++) {
                    uint32_t bq[4], bk[4];
                    LDSM4(bq, bQ + jp * 16 * SROW2 * 2);
                    LDSM4(bk, bK + jp * 16 * SROW2 * 2);
                    MMA(aq[0][2 * jp],     a0, bq[0], bq[1]);
                    MMA(aq[1][2 * jp],     a1, bq[0], bq[1]);
                    MMA(aq[0][2 * jp + 1], a0, bq[2], bq[3]);
                    MMA(aq[1][2 * jp + 1], a1, bq[2], bq[3]);
                    MMA(ak[0][2 * jp],     a0, bk[0], bk[1]);
                    MMA(ak[1][2 * jp],     a1, bk[0], bk[1]);
                    MMA(ak[0][2 * jp + 1], a0, bk[2], bk[3]);
                    MMA(ak[1][2 * jp + 1], a1, bk[2], bk[3]);
                }
            }
            __syncthreads();
        }

        float pj[4];
#pragma unroll
        for (int j = 0; j < 4; j++) {
            const int mi = j >> 1, o = (j & 1) * 2;
            float p = 0.0f;
#pragma unroll
            for (int ni = 0; ni < 4; ni++)
                p += aq[mi][ni][o] * ak[mi][ni][o]
                   + aq[mi][ni][o + 1] * ak[mi][ni][o + 1];
            p += __shfl_xor_sync(0xFFFFFFFF, p, 1);
            p += __shfl_xor_sync(0xFFFFFFFF, p, 2);
            pj[j] = p;
        }

        float* buf = (float*)sm;   // 128 floats
        if (wn == 1 && (lane & 3) == 0) {
#pragma unroll
            for (int j = 0; j < 4; j++)
                buf[(wm * 4 + j) * 8 + (lane >> 2)] = pj[j];
        }
        __syncthreads();
        if (wn == 0 && (lane & 3) == 0) {
            const int h = blockIdx.x;
#pragma unroll
            for (int j = 0; j < 4; j++) {
                float p = pj[j] + buf[(wm * 4 + j) * 8 + (lane >> 2)];
                const int m = m0 + wm * 32 + (lane >> 2) + (j >> 1) * 16 + (j & 1) * 8;
                const int b = m >> 11, q = m & 2047;
                float sd = p * 0.125f;
                int cnt = SEQ - 1 - q;
                float mx = (cnt > 0) ? fmaxf(sd, 0.0f) : sd;
                float ed = expf(sd - mx);
                float eo = (cnt > 0) ? expf(-mx) : 0.0f;
                float Z = ed + (float)cnt * eo;
                g_sa[(b * 8 + h) * SEQ + q] = ed / Z;
                g_sc[(b * 8 + h) * SEQ + q] = eo / Z;
            }
        }
    } else {
        // ================= V branch (fp16x3) ================================
        const int n0 = (blockIdx.x - 8) * 64;
        const __half* gAh = xh + (size_t)(m0 + lrA) * 512 + lpA * 16;
        const __half* gAl = xl + (size_t)(m0 + lrA) * 512 + lpA * 16;
        const __half* gBh = wh + 1024 * 512 + (size_t)(n0 + lrB) * 512 + lpB * 8;
        const __half* gBl = wl + 1024 * 512 + (size_t)(n0 + lrB) * 512 + lpB * 8;

#define LOADCH64(c, bsel) { \
        const uint32_t soff = (uint32_t)(bsel) * (STAGEH * 2); \
        const int ko = (c) * 32; \
        CPASYNC(dA + soff + 0 * A_MAT * 2 + 0,  gAh + ko); \
        CPASYNC(dA + soff + 0 * A_MAT * 2 + 16, gAh + ko + 8); \
        CPASYNC(dA + soff + 1 * A_MAT * 2 + 0,  gAl + ko); \
        CPASYNC(dA + soff + 1 * A_MAT * 2 + 16, gAl + ko + 8); \
        CPASYNC(dB + soff + 2 * A_MAT * 2 + 0,  gBh + ko); \
        CPASYNC(dB + soff + 2 * A_MAT * 2 + B_MAT * 2, gBl + ko); \
    }

        float acc[2][4][4];
#pragma unroll
        for (int i = 0; i < 2; i++)
#pragma unroll
            for (int j = 0; j < 4; j++)
#pragma unroll
                for (int k = 0; k < 4; k++) acc[i][j][k] = 0.0f;

        LOADCH64(0, 0);
        asm volatile("cp.async.commit_group;" ::: "memory");

        for (int c = 0; c < 16; c++) {
            if (c < 15) {
                LOADCH64(c + 1, (c + 1) & 1);
                asm volatile("cp.async.commit_group;" ::: "memory");
                asm volatile("cp.async.wait_group 1;" ::: "memory");
            } else {
                asm volatile("cp.async.wait_group 0;" ::: "memory");
            }
            __syncthreads();

            const uint32_t base = sb + (uint32_t)(c & 1) * (STAGEH * 2);
#pragma unroll
            for (int kk = 0; kk < 2; kk++) {
                const uint32_t aH = base + a_row_off + kk * 32;
                const uint32_t aL = aH + A_MAT * 2;
                uint32_t ah0[4], ah1[4], al0[4], al1[4];
                LDSM4(ah0, aH);
                LDSM4(ah1, aH + 16 * SROW2 * 2);
                LDSM4(al0, aL);
                LDSM4(al1, aL + 16 * SROW2 * 2);

                const uint32_t bH = base + 2 * A_MAT * 2 + b_row_off + kk * 32;
                const uint32_t bL = bH + B_MAT * 2;
#pragma unroll
                for (int jp = 0; jp < 2; jp++) {
                    uint32_t bh[4], bl[4];
                    LDSM4(bh, bH + jp * 16 * SROW2 * 2);
                    LDSM4(bl, bL + jp * 16 * SROW2 * 2);
                    MMA(acc[0][2 * jp],     ah0, bh[0], bh[1]);
                    MMA(acc[1][2 * jp],     ah1, bh[0], bh[1]);
                    MMA(acc[0][2 * jp + 1], ah0, bh[2], bh[3]);
                    MMA(acc[1][2 * jp + 1], ah1, bh[2], bh[3]);
                    MMA(acc[0][2 * jp],     al0, bh[0], bh[1]);
                    MMA(acc[1][2 * jp],     al1, bh[0], bh[1]);
                    MMA(acc[0][2 * jp + 1], al0, bh[2], bh[3]);
                    MMA(acc[1][2 * jp + 1], al1, bh[2], bh[3]);
                    MMA(acc[0][2 * jp],     ah0, bl[0], bl[1]);
                    MMA(acc[1][2 * jp],     ah1, bl[0], bl[1]);
                    MMA(acc[0][2 * jp + 1], ah0, bl[2], bl[3]);
                    MMA(acc[1][2 * jp + 1], ah1, bl[2], bl[3]);
                }
            }
            __syncthreads();
        }

        // Epilogue: fp32 V store
        const int r0 = m0 + wm * 32 + (lane >> 2);
        const int cb2 = n0 + wn * 32 + (lane & 3) * 2;
#pragma unroll
        for (int mi = 0; mi < 2; mi++) {
            const int r = r0 + mi * 16;
#pragma unroll
            for (int ni = 0; ni < 4; ni++) {
                const int cg = cb2 + ni * 8;
                *(float2*)&V[(size_t)r * 512 + cg] =
                    make_float2(acc[mi][ni][0], acc[mi][ni][1]);
                *(float2*)&V[(size_t)(r + 8) * 512 + cg] =
                    make_float2(acc[mi][ni][2], acc[mi][ni][3]);
            }
        }

        // Fine 16-row chunk sums + warp totals for coarse sums
        const int b = m0 >> 11;
        const int c16 = ((m0 & 2047) >> 4) + wm * 2;
        const int h = n0 >> 6;
        const int bh = b * 8 + h;
        float* cbuf = (float*)sm;   // [4 wm][64 dh]
#pragma unroll
        for (int ni = 0; ni < 4; ni++) {
            float t0 = 0.0f, t1 = 0.0f;
#pragma unroll
            for (int mi = 0; mi < 2; mi++) {
                float s0 = acc[mi][ni][0] + acc[mi][ni][2];
                float s1 = acc[mi][ni][1] + acc[mi][ni][3];
#pragma unroll
                for (int st = 4; st < 32; st <<= 1) {
                    s0 += __shfl_xor_sync(0xFFFFFFFF, s0, st);
                    s1 += __shfl_xor_sync(0xFFFFFFFF, s1, st);
                }
                if (lane < 4) {
                    const int dh = wn * 32 + (lane << 1) + ni * 8;
                    *(float2*)&g_cs[((size_t)bh * 128 + c16 + mi) * 64 + dh] =
                        make_float2(s0, s1);
                }
                t0 += s0; t1 += s1;
            }
            if (lane < 4) {
                const int dh = wn * 32 + (lane << 1) + ni * 8;
                cbuf[wm * 64 + dh]     = t0;
                cbuf[wm * 64 + dh + 1] = t1;
            }
        }
        __syncthreads();
        if (tid < 64) {
            const int mblk = (m0 & 2047) >> 7;   // 0..15
            g_cb[((size_t)bh * 16 + mblk) * 64 + tid] =
                cbuf[tid] + cbuf[64 + tid] + cbuf[128 + tid] + cbuf[192 + tid];
        }
    }
}

// ---------------------------------------------------------------------------
// fp16x3 GEMM, CTA tile 128x64, BK=32, 2 CTAs/SM — output projection.
// ---------------------------------------------------------------------------
__global__ __launch_bounds__(256, 2) void gemm64(
    const __half* __restrict__ Ah, const __half* __restrict__ Al,
    const __half* __restrict__ Bh, const __half* __restrict__ Bl,
    float* __restrict__ C)
{
    extern __shared__ __half sm[];
    const uint32_t sb = smem_u32(sm);
    const int tid = threadIdx.x;
    const int lane = tid & 31, wid = tid >> 5;
    const int wm = wid & 3, wn = wid >> 2;
    const int n0 = blockIdx.x * 64, m0 = blockIdx.y * 128;

    const int lrA = tid >> 1, lpA = tid & 1;
    const int lrB = tid >> 2, lpB = tid & 3;
    const __half* gAh = Ah + (size_t)(m0 + lrA) * 512 + lpA * 16;
    const __half* gAl = Al + (size_t)(m0 + lrA) * 512 + lpA * 16;
    const __half* gBh = Bh + (size_t)(n0 + lrB) * 512 + lpB * 8;
    const __half* gBl = Bl + (size_t)(n0 + lrB) * 512 + lpB * 8;
    const uint32_t dA = sb + (uint32_t)(lrA * SROW2 + lpA * 16) * 2;
    const uint32_t dB = sb + (uint32_t)(lrB * SROW2 + lpB * 8) * 2;

#define LOADCHO(c, bsel) { \
        const uint32_t soff = (uint32_t)(bsel) * (STAGEH * 2); \
        const int ko = (c) * 32; \
        CPASYNC(dA + soff + 0 * A_MAT * 2 + 0,  gAh + ko); \
        CPASYNC(dA + soff + 0 * A_MAT * 2 + 16, gAh + ko + 8); \
        CPASYNC(dA + soff + 1 * A_MAT * 2 + 0,  gAl + ko); \
        CPASYNC(dA + soff + 1 * A_MAT * 2 + 16, gAl + ko + 8); \
        CPASYNC(dB + soff + 2 * A_MAT * 2 + 0,  gBh + ko); \
        CPASYNC(dB + soff + 2 * A_MAT * 2 + B_MAT * 2, gBl + ko); \
    }

    float acc[2][4][4];
#pragma unroll
    for (int i = 0; i < 2; i++)
#pragma unroll
        for (int j = 0; j < 4; j++)
#pragma unroll
            for (int k = 0; k < 4; k++) acc[i][j][k] = 0.0f;

    LOADCHO(0, 0);
    asm volatile("cp.async.commit_group;" ::: "memory");

    const uint32_t a_row_off =
        (uint32_t)((wm * 32 + (lane & 15)) * SROW2) * 2 + (uint32_t)((lane >> 4) * 16);
    const int bn = wn * 32 + (lane & 7) + ((lane >> 4) << 3);
    const uint32_t b_row_off =
        (uint32_t)(bn * SROW2) * 2 + (uint32_t)(((lane >> 3) & 1) * 16);

    for (int c = 0; c < 16; c++) {
        if (c < 15) {
            LOADCHO(c + 1, (c + 1) & 1);
            asm volatile("cp.async.commit_group;" ::: "memory");
            asm volatile("cp.async.wait_group 1;" ::: "memory");
        } else {
            asm volatile("cp.async.wait_group 0;" ::: "memory");
        }
        __syncthreads();

        const uint32_t base = sb + (uint32_t)(c & 1) * (STAGEH * 2);
#pragma unroll
        for (int kk = 0; kk < 2; kk++) {
            const uint32_t aH = base + a_row_off + kk * 32;
            const uint32_t aL = aH + A_MAT * 2;
            uint32_t ah0[4], ah1[4], al0[4], al1[4];
            LDSM4(ah0, aH);
            LDSM4(ah1, aH + 16 * SROW2 * 2);
            LDSM4(al0, aL);
            LDSM4(al1, aL + 16 * SROW2 * 2);

            const uint32_t bH = base + 2 * A_MAT * 2 + b_row_off + kk * 32;
            const uint32_t bL = bH + B_MAT * 2;
#pragma unroll
            for (int jp = 0; jp < 2; jp++) {
                uint32_t bh[4], bl[4];
                LDSM4(bh, bH + jp * 16 * SROW2 * 2);
                LDSM4(bl, bL + jp * 16 * SROW2 * 2);
                MMA(acc[0][2 * jp],     ah0, bh[0], bh[1]);
                MMA(acc[1][2 * jp],     ah1, bh[0], bh[1]);
                MMA(acc[0][2 * jp + 1], ah0, bh[2], bh[3]);
                MMA(acc[1][2 * jp + 1], ah1, bh[2], bh[3]);
                MMA(acc[0][2 * jp],     al0, bh[0], bh[1]);
                MMA(acc[1][2 * jp],     al1, bh[0], bh[1]);
                MMA(acc[0][2 * jp + 1], al0, bh[2], bh[3]);
                MMA(acc[1][2 * jp + 1], al1, bh[2], bh[3]);
                MMA(acc[0][2 * jp],     ah0, bl[0], bl[1]);
                MMA(acc[1][2 * jp],     ah1, bl[0], bl[1]);
                MMA(acc[0][2 * jp + 1], ah0, bl[2], bl[3]);
                MMA(acc[1][2 * jp + 1], ah1, bl[2], bl[3]);
            }
        }
        __syncthreads();
    }

    const int r0 = m0 + wm * 32 + (lane >> 2);
    const int cb = n0 + wn * 32 + (lane & 3) * 2;
#pragma unroll
    for (int mi = 0; mi < 2; mi++) {
        const int r = r0 + mi * 16;
#pragma unroll
        for (int ni = 0; ni < 4; ni++) {
            const int cg = cb + ni * 8;
            *(float2*)&C[(size_t)r * 512 + cg] =
                make_float2(acc[mi][ni][0], acc[mi][ni][1]);
            *(float2*)&C[(size_t)(r + 8) * 512 + cg] =
                make_float2(acc[mi][ni][2], acc[mi][ni][3]);
        }
    }
}

// ---------------------------------------------------------------------------
// Scan: z[q] = a_q*v[q] + c_q*suffix_{p>q} v[p]. Run-in from coarse + fine sums.
// ---------------------------------------------------------------------------
__global__ __launch_bounds__(256) void v_scan()
{
    int bh = blockIdx.y;
    int chunk = blockIdx.x * 4 + (threadIdx.x >> 6);   // 0..127
    int dh = threadIdx.x & 63;
    int b = bh >> 3, h = bh & 7;
    const int q0 = chunk * 16;

    // Run-in: coarse 128-row blocks after this chunk's block + fine chunks
    const int cbk = chunk >> 3;
    float run = 0.0f;
    const float* cbp = g_cb + ((size_t)bh * 16) * 64 + dh;
    for (int j = cbk + 1; j < 16; j++) run += cbp[(size_t)j * 64];
    const float* csp = g_cs + ((size_t)bh * 128) * 64 + dh;
    const int cfEnd = (cbk + 1) << 3;
    for (int cf = chunk + 1; cf < cfEnd; cf++) run += csp[(size_t)cf * 64];

    // Batch all loads up front
    const float* vbase = g_V + (size_t)(b * SEQ + q0) * DMODEL + h * DH + dh;
    float v[16];
#pragma unroll
    for (int i = 0; i < 16; i++) v[i] = vbase[i * DMODEL];

    float wa[16], wc[16];
    const float* sa = g_sa + bh * SEQ + q0;
    const float* sc = g_sc + bh * SEQ + q0;
#pragma unroll
    for (int i = 0; i < 16; i++) { wa[i] = sa[i]; wc[i] = sc[i]; }

    __half* zhb = g_zh + (size_t)(b * SEQ + q0) * DMODEL + h * DH + dh;
    __half* zlb = g_zl + (size_t)(b * SEQ + q0) * DMODEL + h * DH + dh;
#pragma unroll
    for (int i = 15; i >= 0; i--) {
        float z = wa[i] * v[i] + wc[i] * run;
        __half zh = __float2half_rn(z);
        zhb[i * DMODEL] = zh;
        zlb[i * DMODEL] = __float2half_rn(z - __half2float(zh));
        run += v[i];
    }
}

// ---------------------------------------------------------------------------
extern "C" void kernel_launch(void* const* d_in, const int* in_sizes, int n_in,
                              void* d_out, int out_size)
{
    const float* x  = (const float*)d_in[0];
    const float* WQ = (const float*)d_in[1];
    const float* WK = (const float*)d_in[2];
    const float* WV = (const float*)d_in[3];
    const float* WO = (const float*)d_in[4];
    float* out = (float*)d_out;

    cudaFuncSetAttribute(qkv_fused, cudaFuncAttributeMaxDynamicSharedMemorySize,
                         SMEM64);
    cudaFuncSetAttribute(gemm64, cudaFuncAttributeMaxDynamicSharedMemorySize,
                         SMEM64);

    __half *xh, *xl, *wh, *wl, *oh, *ol, *zh, *zl;
    float *gv;
    cudaGetSymbolAddress((void**)&xh, g_xh);
    cudaGetSymbolAddress((void**)&xl, g_xl);
    cudaGetSymbolAddress((void**)&wh, g_wh);
    cudaGetSymbolAddress((void**)&wl, g_wl);
    cudaGetSymbolAddress((void**)&oh, g_oh);
    cudaGetSymbolAddress((void**)&ol, g_ol);
    cudaGetSymbolAddress((void**)&zh, g_zh);
    cudaGetSymbolAddress((void**)&zl, g_zl);
    cudaGetSymbolAddress((void**)&gv, g_V);

    convert_all<<<3072, 256>>>(x, WQ, WK, WV, WO);

    // Fused QK-diag (bx 0..7) + V projection (bx 8..15): 512 CTAs
    qkv_fused<<<dim3(16, 32), 256, SMEM64>>>(xh, xl, wh, wl, gv);

    v_scan<<<dim3(32, 16), 256>>>();

    // Output projection (fp16x3)
    gemm64<<<dim3(8, 32), 256, SMEM64>>>(zh, zl, oh, ol, out);
}

// round 14
// speedup vs baseline: 1.2131x; 1.0051x over previous
#include <cuda_runtime.h>
#include <cuda_fp16.h>
#include <math.h>
#include <stdint.h>

#define SEQ     2048
#define DMODEL  512
#define NH      8
#define DH      64
#define BATCH   2
#define MTOT    4096

// ---------------- scratch (__device__ globals, allocation-free) -------------
__device__ __half g_xh[MTOT * DMODEL];
__device__ __half g_xl[MTOT * DMODEL];
__device__ __half g_wh[3 * DMODEL * DMODEL];   // [Wq;Wk;Wv] rows 0..1535 (hi)
__device__ __half g_wl[3 * DMODEL * DMODEL];   // lo used only for Wv range
__device__ __half g_oh[DMODEL * DMODEL];
__device__ __half g_ol[DMODEL * DMODEL];
__device__ float  g_V [MTOT * DMODEL];
__device__ __half g_zh[MTOT * DMODEL];
__device__ __half g_zl[MTOT * DMODEL];
__device__ float  g_sa[16 * SEQ];
__device__ float  g_sc[16 * SEQ];
__device__ float  g_cs[16 * 128 * 64];   // [bh][chunk16][dh] fine V sums
__device__ float  g_cb[16 * 16 * 64];    // [bh][mblk128][dh] coarse V sums

// ---------------------------------------------------------------------------
__device__ __forceinline__ uint32_t smem_u32(const void* p) {
    uint32_t a;
    asm("{ .reg .u64 t; cvta.to.shared.u64 t, %1; cvt.u32.u64 %0, t; }"
        : "=r"(a) : "l"(p));
    return a;
}

#define CPASYNC(d, s) \
    asm volatile("cp.async.cg.shared.global [%0], [%1], 16;" \
                 :: "r"(d), "l"(s) : "memory")

#define LDSM4(r, a) \
    asm volatile("ldmatrix.sync.aligned.m8n8.x4.shared.b16 {%0,%1,%2,%3}, [%4];" \
                 : "=r"((r)[0]), "=r"((r)[1]), "=r"((r)[2]), "=r"((r)[3]) \
                 : "r"(a))

#define MMA(d, a, b0, b1) \
    asm volatile("mma.sync.aligned.m16n8k16.row.col.f32.f16.f16.f32 " \
                 "{%0,%1,%2,%3},{%4,%5,%6,%7},{%8,%9},{%0,%1,%2,%3};" \
                 : "+f"((d)[0]), "+f"((d)[1]), "+f"((d)[2]), "+f"((d)[3]) \
                 : "r"((a)[0]), "r"((a)[1]), "r"((a)[2]), "r"((a)[3]), \
                   "r"(b0), "r"(b1))

// 128x64 BK=32 tiling, 3-stage pipeline
#define SROW2 40                         // 32 halves + 8 pad
#define A_MAT (128 * SROW2)              // halves
#define B_MAT (64 * SROW2)
#define STAGEH (2 * A_MAT + 2 * B_MAT)   // V/out stage (Ah,Al,Bh,Bl) halves
#define SMEM64 (3 * STAGEH * 2)          // 92160 B
#define STAGEQK (A_MAT + 2 * B_MAT)      // QK stage (A,BQ,BK) halves

// ---------------------------------------------------------------------------
// fp32 -> fp16 hi/lo conversion (lo skipped for Wq/Wk)
// ---------------------------------------------------------------------------
__global__ __launch_bounds__(256) void convert_all(
    const float* __restrict__ x,  const float* __restrict__ wq,
    const float* __restrict__ wk, const float* __restrict__ wv,
    const float* __restrict__ wo)
{
    int t = blockIdx.x * 256 + threadIdx.x;       // float4 index, 786432 total
    const float* src;
    __half *dh, *dl;
    int idx;
    bool wantLo = true;
    if (t < 524288)      { src = x;  dh = g_xh;          dl = g_xl;          idx = t; }
    else if (t < 589824) { src = wq; dh = g_wh;          dl = g_wl;          idx = t - 524288; wantLo = false; }
    else if (t < 655360) { src = wk; dh = g_wh + 262144; dl = g_wl + 262144; idx = t - 589824; wantLo = false; }
    else if (t < 720896) { src = wv; dh = g_wh + 524288; dl = g_wl + 524288; idx = t - 655360; }
    else                 { src = wo; dh = g_oh;          dl = g_ol;          idx = t - 720896; }

    float4 v = ((const float4*)src)[idx];
    __half h0 = __float2half_rn(v.x), h1 = __float2half_rn(v.y);
    __half h2 = __float2half_rn(v.z), h3 = __float2half_rn(v.w);
    __half2* ph = (__half2*)(dh + idx * 4);
    ph[0] = __halves2half2(h0, h1); ph[1] = __halves2half2(h2, h3);
    if (wantLo) {
        __half l0 = __float2half_rn(v.x - __half2float(h0));
        __half l1 = __float2half_rn(v.y - __half2float(h1));
        __half l2 = __float2half_rn(v.z - __half2float(h2));
        __half l3 = __float2half_rn(v.w - __half2float(h3));
        __half2* pl = (__half2*)(dl + idx * 4);
        pl[0] = __halves2half2(l0, l1); pl[1] = __halves2half2(l2, l3);
    }
}

// ---------------------------------------------------------------------------
// Fused QK-diag + V-projection. grid (16, 32), both 128x64/BK=32, 3-stage,
// ONE barrier per chunk, 2 CTAs/SM.
// ---------------------------------------------------------------------------
__global__ __launch_bounds__(256, 2) void qkv_fused(
    const __half* __restrict__ xh, const __half* __restrict__ xl,
    const __half* __restrict__ wh, const __half* __restrict__ wl,
    float* __restrict__ V)
{
    extern __shared__ __half sm[];
    const uint32_t sb = smem_u32(sm);
    const int tid = threadIdx.x;
    const int lane = tid & 31, wid = tid >> 5;
    const int wm = wid & 3, wn = wid >> 2;
    const int m0 = blockIdx.y * 128;

    const int lrA = tid >> 1, lpA = tid & 1;
    const int lrB = tid >> 2, lpB = tid & 3;
    const uint32_t dA = sb + (uint32_t)(lrA * SROW2 + lpA * 16) * 2;
    const uint32_t dB = sb + (uint32_t)(lrB * SROW2 + lpB * 8) * 2;

    const uint32_t a_row_off =
        (uint32_t)((wm * 32 + (lane & 15)) * SROW2) * 2 + (uint32_t)((lane >> 4) * 16);
    const int bn = wn * 32 + (lane & 7) + ((lane >> 4) << 3);
    const uint32_t b_row_off =
        (uint32_t)(bn * SROW2) * 2 + (uint32_t)(((lane >> 3) & 1) * 16);

    if (blockIdx.x < 8) {
        // ================= QK-diagonal branch (plain fp16) ==================
        const int n0 = blockIdx.x * 64;   // head = blockIdx.x
        const __half* gA = xh + (size_t)(m0 + lrA) * 512 + lpA * 16;
        const __half* gQ = wh + (size_t)(n0 + lrB) * 512 + lpB * 8;
        const __half* gK = wh + 512 * 512 + (size_t)(n0 + lrB) * 512 + lpB * 8;

#define LOADQK(c, s) { \
        const uint32_t soff = (uint32_t)(s) * (STAGEQK * 2); \
        const int ko = (c) * 32; \
        CPASYNC(dA + soff + 0,  gA + ko); \
        CPASYNC(dA + soff + 16, gA + ko + 8); \
        CPASYNC(dB + soff + A_MAT * 2, gQ + ko); \
        CPASYNC(dB + soff + A_MAT * 2 + B_MAT * 2, gK + ko); \
    }

        float aq[2][4][4], ak[2][4][4];
#pragma unroll
        for (int i = 0; i < 2; i++)
#pragma unroll
            for (int j = 0; j < 4; j++)
#pragma unroll
                for (int k = 0; k < 4; k++) { aq[i][j][k] = 0.0f; ak[i][j][k] = 0.0f; }

        LOADQK(0, 0);
        asm volatile("cp.async.commit_group;" ::: "memory");
        LOADQK(1, 1);
        asm volatile("cp.async.commit_group;" ::: "memory");

        for (int c = 0; c < 16; c++) {
            if (c < 15) {
                asm volatile("cp.async.wait_group 1;" ::: "memory");
            } else {
                asm volatile("cp.async.wait_group 0;" ::: "memory");
            }
            __syncthreads();
            if (c < 14) {
                LOADQK(c + 2, (c + 2) % 3);
                asm volatile("cp.async.commit_group;" ::: "memory");
            }

            const uint32_t base = sb + (uint32_t)(c % 3) * (STAGEQK * 2);
#pragma unroll
            for (int kk = 0; kk < 2; kk++) {
                const uint32_t aA = base + a_row_off + kk * 32;
                uint32_t a0[4], a1[4];
                LDSM4(a0, aA);
                LDSM4(a1, aA + 16 * SROW2 * 2);

                const uint32_t bQ = base + A_MAT * 2 + b_row_off + kk * 32;
                const uint32_t bK = bQ + B_MAT * 2;
#pragma unroll
                for (int jp = 0; jp < 2; jp++) {
                    uint32_t bq[4], bk[4];
                    LDSM4(bq, bQ + jp * 16 * SROW2 * 2);
                    LDSM4(bk, bK + jp * 16 * SROW2 * 2);
                    MMA(aq[0][2 * jp],     a0, bq[0], bq[1]);
                    MMA(aq[1][2 * jp],     a1, bq[0], bq[1]);
                    MMA(aq[0][2 * jp + 1], a0, bq[2], bq[3]);
                    MMA(aq[1][2 * jp + 1], a1, bq[2], bq[3]);
                    MMA(ak[0][2 * jp],     a0, bk[0], bk[1]);
                    MMA(ak[1][2 * jp],     a1, bk[0], bk[1]);
                    MMA(ak[0][2 * jp + 1], a0, bk[2], bk[3]);
                    MMA(ak[1][2 * jp + 1], a1, bk[2], bk[3]);
                }
            }
        }
        __syncthreads();

        float pj[4];
#pragma unroll
        for (int j = 0; j < 4; j++) {
            const int mi = j >> 1, o = (j & 1) * 2;
            float p = 0.0f;
#pragma unroll
            for (int ni = 0; ni < 4; ni++)
                p += aq[mi][ni][o] * ak[mi][ni][o]
                   + aq[mi][ni][o + 1] * ak[mi][ni][o + 1];
            p += __shfl_xor_sync(0xFFFFFFFF, p, 1);
            p += __shfl_xor_sync(0xFFFFFFFF, p, 2);
            pj[j] = p;
        }

        float* buf = (float*)sm;   // 128 floats
        if (wn == 1 && (lane & 3) == 0) {
#pragma unroll
            for (int j = 0; j < 4; j++)
                buf[(wm * 4 + j) * 8 + (lane >> 2)] = pj[j];
        }
        __syncthreads();
        if (wn == 0 && (lane & 3) == 0) {
            const int h = blockIdx.x;
#pragma unroll
            for (int j = 0; j < 4; j++) {
                float p = pj[j] + buf[(wm * 4 + j) * 8 + (lane >> 2)];
                const int m = m0 + wm * 32 + (lane >> 2) + (j >> 1) * 16 + (j & 1) * 8;
                const int b = m >> 11, q = m & 2047;
                float sd = p * 0.125f;
                int cnt = SEQ - 1 - q;
                float mx = (cnt > 0) ? fmaxf(sd, 0.0f) : sd;
                float ed = expf(sd - mx);
                float eo = (cnt > 0) ? expf(-mx) : 0.0f;
                float Z = ed + (float)cnt * eo;
                g_sa[(b * 8 + h) * SEQ + q] = ed / Z;
                g_sc[(b * 8 + h) * SEQ + q] = eo / Z;
            }
        }
    } else {
        // ================= V branch (fp16x3) ================================
        const int n0 = (blockIdx.x - 8) * 64;
        const __half* gAh = xh + (size_t)(m0 + lrA) * 512 + lpA * 16;
        const __half* gAl = xl + (size_t)(m0 + lrA) * 512 + lpA * 16;
        const __half* gBh = wh + 1024 * 512 + (size_t)(n0 + lrB) * 512 + lpB * 8;
        const __half* gBl = wl + 1024 * 512 + (size_t)(n0 + lrB) * 512 + lpB * 8;

#define LOADCH64(c, s) { \
        const uint32_t soff = (uint32_t)(s) * (STAGEH * 2); \
        const int ko = (c) * 32; \
        CPASYNC(dA + soff + 0 * A_MAT * 2 + 0,  gAh + ko); \
        CPASYNC(dA + soff + 0 * A_MAT * 2 + 16, gAh + ko + 8); \
        CPASYNC(dA + soff + 1 * A_MAT * 2 + 0,  gAl + ko); \
        CPASYNC(dA + soff + 1 * A_MAT * 2 + 16, gAl + ko + 8); \
        CPASYNC(dB + soff + 2 * A_MAT * 2 + 0,  gBh + ko); \
        CPASYNC(dB + soff + 2 * A_MAT * 2 + B_MAT * 2, gBl + ko); \
    }

        float acc[2][4][4];
#pragma unroll
        for (int i = 0; i < 2; i++)
#pragma unroll
            for (int j = 0; j < 4; j++)
#pragma unroll
                for (int k = 0; k < 4; k++) acc[i][j][k] = 0.0f;

        LOADCH64(0, 0);
        asm volatile("cp.async.commit_group;" ::: "memory");
        LOADCH64(1, 1);
        asm volatile("cp.async.commit_group;" ::: "memory");

        for (int c = 0; c < 16; c++) {
            if (c < 15) {
                asm volatile("cp.async.wait_group 1;" ::: "memory");
            } else {
                asm volatile("cp.async.wait_group 0;" ::: "memory");
            }
            __syncthreads();
            if (c < 14) {
                LOADCH64(c + 2, (c + 2) % 3);
                asm volatile("cp.async.commit_group;" ::: "memory");
            }

            const uint32_t base = sb + (uint32_t)(c % 3) * (STAGEH * 2);
#pragma unroll
            for (int kk = 0; kk < 2; kk++) {
                const uint32_t aH = base + a_row_off + kk * 32;
                const uint32_t aL = aH + A_MAT * 2;
                uint32_t ah0[4], ah1[4], al0[4], al1[4];
                LDSM4(ah0, aH);
                LDSM4(ah1, aH + 16 * SROW2 * 2);
                LDSM4(al0, aL);
                LDSM4(al1, aL + 16 * SROW2 * 2);

                const uint32_t bH = base + 2 * A_MAT * 2 + b_row_off + kk * 32;
                const uint32_t bL = bH + B_MAT * 2;
#pragma unroll
                for (int jp = 0; jp < 2; jp++) {
                    uint32_t bh[4], bl[4];
                    LDSM4(bh, bH + jp * 16 * SROW2 * 2);
                    LDSM4(bl, bL + jp * 16 * SROW2 * 2);
                    MMA(acc[0][2 * jp],     ah0, bh[0], bh[1]);
                    MMA(acc[1][2 * jp],     ah1, bh[0], bh[1]);
                    MMA(acc[0][2 * jp + 1], ah0, bh[2], bh[3]);
                    MMA(acc[1][2 * jp + 1], ah1, bh[2], bh[3]);
                    MMA(acc[0][2 * jp],     al0, bh[0], bh[1]);
                    MMA(acc[1][2 * jp],     al1, bh[0], bh[1]);
                    MMA(acc[0][2 * jp + 1], al0, bh[2], bh[3]);
                    MMA(acc[1][2 * jp + 1], al1, bh[2], bh[3]);
                    MMA(acc[0][2 * jp],     ah0, bl[0], bl[1]);
                    MMA(acc[1][2 * jp],     ah1, bl[0], bl[1]);
                    MMA(acc[0][2 * jp + 1], ah0, bl[2], bl[3]);
                    MMA(acc[1][2 * jp + 1], ah1, bl[2], bl[3]);
                }
            }
        }
        __syncthreads();

        // Epilogue: fp32 V store
        const int r0 = m0 + wm * 32 + (lane >> 2);
        const int cb2 = n0 + wn * 32 + (lane & 3) * 2;
#pragma unroll
        for (int mi = 0; mi < 2; mi++) {
            const int r = r0 + mi * 16;
#pragma unroll
            for (int ni = 0; ni < 4; ni++) {
                const int cg = cb2 + ni * 8;
                *(float2*)&V[(size_t)r * 512 + cg] =
                    make_float2(acc[mi][ni][0], acc[mi][ni][1]);
                *(float2*)&V[(size_t)(r + 8) * 512 + cg] =
                    make_float2(acc[mi][ni][2], acc[mi][ni][3]);
            }
        }

        // Fine 16-row chunk sums + coarse 128-row sums
        const int b = m0 >> 11;
        const int c16 = ((m0 & 2047) >> 4) + wm * 2;
        const int h = n0 >> 6;
        const int bh = b * 8 + h;
        float* cbuf = (float*)sm;   // [4 wm][64 dh]
#pragma unroll
        for (int ni = 0; ni < 4; ni++) {
            float t0 = 0.0f, t1 = 0.0f;
#pragma unroll
            for (int mi = 0; mi < 2; mi++) {
                float s0 = acc[mi][ni][0] + acc[mi][ni][2];
                float s1 = acc[mi][ni][1] + acc[mi][ni][3];
#pragma unroll
                for (int st = 4; st < 32; st <<= 1) {
                    s0 += __shfl_xor_sync(0xFFFFFFFF, s0, st);
                    s1 += __shfl_xor_sync(0xFFFFFFFF, s1, st);
                }
                if (lane < 4) {
                    const int dh = wn * 32 + (lane << 1) + ni * 8;
                    *(float2*)&g_cs[((size_t)bh * 128 + c16 + mi) * 64 + dh] =
                        make_float2(s0, s1);
                }
                t0 += s0; t1 += s1;
            }
            if (lane < 4) {
                const int dh = wn * 32 + (lane << 1) + ni * 8;
                cbuf[wm * 64 + dh]     = t0;
                cbuf[wm * 64 + dh + 1] = t1;
            }
        }
        __syncthreads();
        if (tid < 64) {
            const int mblk = (m0 & 2047) >> 7;   // 0..15
            g_cb[((size_t)bh * 16 + mblk) * 64 + tid] =
                cbuf[tid] + cbuf[64 + tid] + cbuf[128 + tid] + cbuf[192 + tid];
        }
    }
}

// ---------------------------------------------------------------------------
// fp16x3 GEMM, 128x64/BK=32, 3-stage, one barrier per chunk — out projection.
// ---------------------------------------------------------------------------
__global__ __launch_bounds__(256, 2) void gemm64(
    const __half* __restrict__ Ah, const __half* __restrict__ Al,
    const __half* __restrict__ Bh, const __half* __restrict__ Bl,
    float* __restrict__ C)
{
    extern __shared__ __half sm[];
    const uint32_t sb = smem_u32(sm);
    const int tid = threadIdx.x;
    const int lane = tid & 31, wid = tid >> 5;
    const int wm = wid & 3, wn = wid >> 2;
    const int n0 = blockIdx.x * 64, m0 = blockIdx.y * 128;

    const int lrA = tid >> 1, lpA = tid & 1;
    const int lrB = tid >> 2, lpB = tid & 3;
    const __half* gAh = Ah + (size_t)(m0 + lrA) * 512 + lpA * 16;
    const __half* gAl = Al + (size_t)(m0 + lrA) * 512 + lpA * 16;
    const __half* gBh = Bh + (size_t)(n0 + lrB) * 512 + lpB * 8;
    const __half* gBl = Bl + (size_t)(n0 + lrB) * 512 + lpB * 8;
    const uint32_t dA = sb + (uint32_t)(lrA * SROW2 + lpA * 16) * 2;
    const uint32_t dB = sb + (uint32_t)(lrB * SROW2 + lpB * 8) * 2;

#define LOADCHO(c, s) { \
        const uint32_t soff = (uint32_t)(s) * (STAGEH * 2); \
        const int ko = (c) * 32; \
        CPASYNC(dA + soff + 0 * A_MAT * 2 + 0,  gAh + ko); \
        CPASYNC(dA + soff + 0 * A_MAT * 2 + 16, gAh + ko + 8); \
        CPASYNC(dA + soff + 1 * A_MAT * 2 + 0,  gAl + ko); \
        CPASYNC(dA + soff + 1 * A_MAT * 2 + 16, gAl + ko + 8); \
        CPASYNC(dB + soff + 2 * A_MAT * 2 + 0,  gBh + ko); \
        CPASYNC(dB + soff + 2 * A_MAT * 2 + B_MAT * 2, gBl + ko); \
    }

    float acc[2][4][4];
#pragma unroll
    for (int i = 0; i < 2; i++)
#pragma unroll
        for (int j = 0; j < 4; j++)
#pragma unroll
            for (int k = 0; k < 4; k++) acc[i][j][k] = 0.0f;

    LOADCHO(0, 0);
    asm volatile("cp.async.commit_group;" ::: "memory");
    LOADCHO(1, 1);
    asm volatile("cp.async.commit_group;" ::: "memory");

    const uint32_t a_row_off =
        (uint32_t)((wm * 32 + (lane & 15)) * SROW2) * 2 + (uint32_t)((lane >> 4) * 16);
    const int bn = wn * 32 + (lane & 7) + ((lane >> 4) << 3);
    const uint32_t b_row_off =
        (uint32_t)(bn * SROW2) * 2 + (uint32_t)(((lane >> 3) & 1) * 16);

    for (int c = 0; c < 16; c++) {
        if (c < 15) {
            asm volatile("cp.async.wait_group 1;" ::: "memory");
        } else {
            asm volatile("cp.async.wait_group 0;" ::: "memory");
        }
        __syncthreads();
        if (c < 14) {
            LOADCHO(c + 2, (c + 2) % 3);
            asm volatile("cp.async.commit_group;" ::: "memory");
        }

        const uint32_t base = sb + (uint32_t)(c % 3) * (STAGEH * 2);
#pragma unroll
        for (int kk = 0; kk < 2; kk++) {
            const uint32_t aH = base + a_row_off + kk * 32;
            const uint32_t aL = aH + A_MAT * 2;
            uint32_t ah0[4], ah1[4], al0[4], al1[4];
            LDSM4(ah0, aH);
            LDSM4(ah1, aH + 16 * SROW2 * 2);
            LDSM4(al0, aL);
            LDSM4(al1, aL + 16 * SROW2 * 2);

            const uint32_t bH = base + 2 * A_MAT * 2 + b_row_off + kk * 32;
            const uint32_t bL = bH + B_MAT * 2;
#pragma unroll
            for (int jp = 0; jp < 2; jp++) {
                uint32_t bh[4], bl[4];
                LDSM4(bh, bH + jp * 16 * SROW2 * 2);
                LDSM4(bl, bL + jp * 16 * SROW2 * 2);
                MMA(acc[0][2 * jp],     ah0, bh[0], bh[1]);
                MMA(acc[1][2 * jp],     ah1, bh[0], bh[1]);
                MMA(acc[0][2 * jp + 1], ah0, bh[2], bh[3]);
                MMA(acc[1][2 * jp + 1], ah1, bh[2], bh[3]);
                MMA(acc[0][2 * jp],     al0, bh[0], bh[1]);
                MMA(acc[1][2 * jp],     al1, bh[0], bh[1]);
                MMA(acc[0][2 * jp + 1], al0, bh[2], bh[3]);
                MMA(acc[1][2 * jp + 1], al1, bh[2], bh[3]);
                MMA(acc[0][2 * jp],     ah0, bl[0], bl[1]);
                MMA(acc[1][2 * jp],     ah1, bl[0], bl[1]);
                MMA(acc[0][2 * jp + 1], ah0, bl[2], bl[3]);
                MMA(acc[1][2 * jp + 1], ah1, bl[2], bl[3]);
            }
        }
    }

    const int r0 = m0 + wm * 32 + (lane >> 2);
    const int cb = n0 + wn * 32 + (lane & 3) * 2;
#pragma unroll
    for (int mi = 0; mi < 2; mi++) {
        const int r = r0 + mi * 16;
#pragma unroll
        for (int ni = 0; ni < 4; ni++) {
            const int cg = cb + ni * 8;
            *(float2*)&C[(size_t)r * 512 + cg] =
                make_float2(acc[mi][ni][0], acc[mi][ni][1]);
            *(float2*)&C[(size_t)(r + 8) * 512 + cg] =
                make_float2(acc[mi][ni][2], acc[mi][ni][3]);
        }
    }
}

// ---------------------------------------------------------------------------
// Scan: z[q] = a_q*v[q] + c_q*suffix_{p>q} v[p]. Run-in from coarse + fine sums.
// ---------------------------------------------------------------------------
__global__ __launch_bounds__(256) void v_scan()
{
    int bh = blockIdx.y;
    int chunk = blockIdx.x * 4 + (threadIdx.x >> 6);   // 0..127
    int dh = threadIdx.x & 63;
    int b = bh >> 3, h = bh & 7;
    const int q0 = chunk * 16;

    // Run-in: coarse 128-row blocks after this chunk's block + fine chunks
    const int cbk = chunk >> 3;
    float run = 0.0f;
    const float* cbp = g_cb + ((size_t)bh * 16) * 64 + dh;
    for (int j = cbk + 1; j < 16; j++) run += cbp[(size_t)j * 64];
    const float* csp = g_cs + ((size_t)bh * 128) * 64 + dh;
    const int cfEnd = (cbk + 1) << 3;
    for (int cf = chunk + 1; cf < cfEnd; cf++) run += csp[(size_t)cf * 64];

    // Batch all loads up front
    const float* vbase = g_V + (size_t)(b * SEQ + q0) * DMODEL + h * DH + dh;
    float v[16];
#pragma unroll
    for (int i = 0; i < 16; i++) v[i] = vbase[i * DMODEL];

    float wa[16], wc[16];
    const float* sa = g_sa + bh * SEQ + q0;
    const float* sc = g_sc + bh * SEQ + q0;
#pragma unroll
    for (int i = 0; i < 16; i++) { wa[i] = sa[i]; wc[i] = sc[i]; }

    __half* zhb = g_zh + (size_t)(b * SEQ + q0) * DMODEL + h * DH + dh;
    __half* zlb = g_zl + (size_t)(b * SEQ + q0) * DMODEL + h * DH + dh;
#pragma unroll
    for (int i = 15; i >= 0; i--) {
        float z = wa[i] * v[i] + wc[i] * run;
        __half zh = __float2half_rn(z);
        zhb[i * DMODEL] = zh;
        zlb[i * DMODEL] = __float2half_rn(z - __half2float(zh));
        run += v[i];
    }
}

// ---------------------------------------------------------------------------
extern "C" void kernel_launch(void* const* d_in, const int* in_sizes, int n_in,
                              void* d_out, int out_size)
{
    const float* x  = (const float*)d_in[0];
    const float* WQ = (const float*)d_in[1];
    const float* WK = (const float*)d_in[2];
    const float* WV = (const float*)d_in[3];
    const float* WO = (const float*)d_in[4];
    float* out = (float*)d_out;

    cudaFuncSetAttribute(qkv_fused, cudaFuncAttributeMaxDynamicSharedMemorySize,
                         SMEM64);
    cudaFuncSetAttribute(gemm64, cudaFuncAttributeMaxDynamicSharedMemorySize,
                         SMEM64);

    __half *xh, *xl, *wh, *wl, *oh, *ol, *zh, *zl;
    float *gv;
    cudaGetSymbolAddress((void**)&xh, g_xh);
    cudaGetSymbolAddress((void**)&xl, g_xl);
    cudaGetSymbolAddress((void**)&wh, g_wh);
    cudaGetSymbolAddress((void**)&wl, g_wl);
    cudaGetSymbolAddress((void**)&oh, g_oh);
    cudaGetSymbolAddress((void**)&ol, g_ol);
    cudaGetSymbolAddress((void**)&zh, g_zh);
    cudaGetSymbolAddress((void**)&zl, g_zl);
    cudaGetSymbolAddress((void**)&gv, g_V);

    convert_all<<<3072, 256>>>(x, WQ, WK, WV, WO);

    // Fused QK-diag (bx 0..7) + V projection (bx 8..15): 512 CTAs
    qkv_fused<<<dim3(16, 32), 256, SMEM64>>>(xh, xl, wh, wl, gv);

    v_scan<<<dim3(32, 16), 256>>>();

    // Output projection (fp16x3)
    gemm64<<<dim3(8, 32), 256, SMEM64>>>(zh, zl, oh, ol, out);
}